// round 8
// baseline (speedup 1.0000x reference)
#include <cuda_runtime.h>
#include <cstdint>

// ---------------- problem constants ----------------
#define NNODES 50000
#define NEDGES 400000
#define NEG_SLOPE 0.2f
#define EPS 1e-5f
#define FULLMASK 0xffffffffu

// ---------------- scratch (device globals; no allocs allowed) ----------------
__device__ float g_h  [NNODES * 256];
__device__ float g_x  [NNODES * 256];
__device__ float g_esrc[NNODES * 4];
__device__ float g_edst[NNODES * 4];
__device__ float g_stats[1024];         // [sum|sumsq|scale|shift] x 256
__device__ int   g_deg[NNODES];
__device__ int   g_off[NNODES + 1];
__device__ int   g_pos[NNODES];
__device__ int   g_csr[NEDGES];
__device__ int   g_hist[256];
__device__ int   g_hpos[256];
__device__ int   g_perm[NNODES];        // nodes sorted by descending degree

// ---------------- helpers ----------------------------------------------------
__device__ __forceinline__ uint32_t f2tf32(float x) {
    uint32_t u;
    asm("cvt.rna.tf32.f32 %0, %1;" : "=r"(u) : "f"(x));
    return u;
}

__device__ __forceinline__ void mma_tf32(float& c0, float& c1, float& c2, float& c3,
                                         uint32_t a0, uint32_t a1, uint32_t a2, uint32_t a3,
                                         uint32_t b0, uint32_t b1) {
    asm volatile(
        "mma.sync.aligned.m16n8k8.row.col.f32.tf32.tf32.f32 "
        "{%0,%1,%2,%3}, {%4,%5,%6,%7}, {%8,%9}, {%0,%1,%2,%3};"
        : "+f"(c0), "+f"(c1), "+f"(c2), "+f"(c3)
        : "r"(a0), "r"(a1), "r"(a2), "r"(a3), "r"(b0), "r"(b1));
}

__device__ __forceinline__ float leaky_exp(float e) {
    e = (e > 0.f) ? e : NEG_SLOPE * e;
    return __expf(e);
}

// ---------------- CSR build --------------------------------------------------
__global__ void csr_count(const int* __restrict__ dst, int* __restrict__ deg)
{
    int e = blockIdx.x * blockDim.x + threadIdx.x;
    if (e < NEDGES) atomicAdd(&deg[dst[e]], 1);
}

__global__ void csr_scan(const int* __restrict__ deg, int* __restrict__ off,
                         int* __restrict__ pos)
{
    const int CHUNK = (NNODES + 1023) / 1024;
    __shared__ int ss[1024];
    int t = threadIdx.x;
    int base = t * CHUNK;
    int s = 0;
    for (int k = 0; k < CHUNK; k++) {
        int i = base + k;
        if (i < NNODES) s += deg[i];
    }
    ss[t] = s;
    __syncthreads();
    for (int o = 1; o < 1024; o <<= 1) {
        int v = (t >= o) ? ss[t - o] : 0;
        __syncthreads();
        ss[t] += v;
        __syncthreads();
    }
    int run = (t > 0) ? ss[t - 1] : 0;
    for (int k = 0; k < CHUNK; k++) {
        int i = base + k;
        if (i < NNODES) {
            off[i] = run;
            pos[i] = run;
            run += deg[i];
        }
    }
    if (t == 1023) off[NNODES] = ss[1023];
}

__global__ void csr_fill(const int* __restrict__ src, const int* __restrict__ dst,
                         int* __restrict__ pos, int* __restrict__ csr)
{
    int e = blockIdx.x * blockDim.x + threadIdx.x;
    if (e < NEDGES) {
        int p = atomicAdd(&pos[dst[e]], 1);
        csr[p] = src[e];
    }
}

// ---------------- degree-balanced permutation (LPT scheduling) ---------------
__global__ void deg_hist(const int* __restrict__ deg, int* __restrict__ hist)
{
    int n = blockIdx.x * blockDim.x + threadIdx.x;
    if (n < NNODES) atomicAdd(&hist[min(deg[n], 255)], 1);
}

__global__ void hist_scan(const int* __restrict__ hist, int* __restrict__ hpos)
{
    __shared__ int sh[256];
    int t = threadIdx.x;
    sh[t] = hist[255 - t];              // reversed: descending degree order
    __syncthreads();
    int val = sh[t];
    for (int o = 1; o < 256; o <<= 1) {
        int v = (t >= o) ? sh[t - o] : 0;
        __syncthreads();
        sh[t] += v;
        __syncthreads();
    }
    hpos[255 - t] = sh[t] - val;        // exclusive prefix (descending)
}

__global__ void perm_fill(const int* __restrict__ deg, int* __restrict__ hpos,
                          int* __restrict__ perm)
{
    int n = blockIdx.x * blockDim.x + threadIdx.x;
    if (n < NNODES) {
        int p = atomicAdd(&hpos[min(deg[n], 255)], 1);
        perm[p] = n;
    }
}

// ---------------- tf32 tensor-core GEMM + fused attn-score epilogue ----------
template <int NORM, int HEADS>
__global__ void gemm_tf32(const float* __restrict__ X, const float* __restrict__ W,
                          float* __restrict__ C, int Nrows, int K, int M,
                          const float* __restrict__ scale, const float* __restrict__ shift,
                          const float* __restrict__ a_srcv, const float* __restrict__ a_dstv,
                          float* __restrict__ esrc, float* __restrict__ edst)
{
    __shared__ float As[128][36];
    __shared__ float Bs[128][36];

    const int tid = threadIdx.x;
    const int rowBase = blockIdx.y * 128;
    const int colBase = blockIdx.x * 128;
    const int warp = tid >> 5;
    const int lane = tid & 31;
    const int wr = (warp & 3) * 32;
    const int wc = (warp >> 2) * 64;
    const int grp = lane >> 2;
    const int tig = lane & 3;

    float c[2][8][4];
#pragma unroll
    for (int t = 0; t < 2; t++)
#pragma unroll
        for (int u = 0; u < 8; u++)
#pragma unroll
            for (int v = 0; v < 4; v++) c[t][u][v] = 0.f;

    for (int k0 = 0; k0 < K; k0 += 32) {
#pragma unroll
        for (int l = 0; l < 4; l++) {
            int idx = tid + l * 256;
            int r = idx >> 3;
            int kk = (idx & 7) * 4;
            int gr = rowBase + r;
            float4 v = make_float4(0.f, 0.f, 0.f, 0.f);
            if (gr < Nrows)
                v = *reinterpret_cast<const float4*>(X + (size_t)gr * K + k0 + kk);
            if (NORM) {
                float4 sc = *reinterpret_cast<const float4*>(scale + k0 + kk);
                float4 sh = *reinterpret_cast<const float4*>(shift + k0 + kk);
                v.x = fmaxf(fmaf(sc.x, v.x, sh.x), 0.f);
                v.y = fmaxf(fmaf(sc.y, v.y, sh.y), 0.f);
                v.z = fmaxf(fmaf(sc.z, v.z, sh.z), 0.f);
                v.w = fmaxf(fmaf(sc.w, v.w, sh.w), 0.f);
            }
            As[r][kk + 0] = __uint_as_float(f2tf32(v.x));
            As[r][kk + 1] = __uint_as_float(f2tf32(v.y));
            As[r][kk + 2] = __uint_as_float(f2tf32(v.z));
            As[r][kk + 3] = __uint_as_float(f2tf32(v.w));
        }
#pragma unroll
        for (int l = 0; l < 4; l++) {
            int idx = tid + l * 256;
            int r = idx >> 3;
            int kk = (idx & 7) * 4;
            float4 v = *reinterpret_cast<const float4*>(W + (size_t)(colBase + r) * K + k0 + kk);
            Bs[r][kk + 0] = __uint_as_float(f2tf32(v.x));
            Bs[r][kk + 1] = __uint_as_float(f2tf32(v.y));
            Bs[r][kk + 2] = __uint_as_float(f2tf32(v.z));
            Bs[r][kk + 3] = __uint_as_float(f2tf32(v.w));
        }
        __syncthreads();

#pragma unroll
        for (int kk = 0; kk < 32; kk += 8) {
            uint32_t a[2][4];
#pragma unroll
            for (int t = 0; t < 2; t++) {
                int r0 = wr + t * 16 + grp;
                a[t][0] = __float_as_uint(As[r0][kk + tig]);
                a[t][1] = __float_as_uint(As[r0 + 8][kk + tig]);
                a[t][2] = __float_as_uint(As[r0][kk + tig + 4]);
                a[t][3] = __float_as_uint(As[r0 + 8][kk + tig + 4]);
            }
            uint32_t b[8][2];
#pragma unroll
            for (int u = 0; u < 8; u++) {
                int cB = wc + u * 8 + grp;
                b[u][0] = __float_as_uint(Bs[cB][kk + tig]);
                b[u][1] = __float_as_uint(Bs[cB][kk + tig + 4]);
            }
#pragma unroll
            for (int t = 0; t < 2; t++)
#pragma unroll
                for (int u = 0; u < 8; u++)
                    mma_tf32(c[t][u][0], c[t][u][1], c[t][u][2], c[t][u][3],
                             a[t][0], a[t][1], a[t][2], a[t][3], b[u][0], b[u][1]);
        }
        __syncthreads();
    }

#pragma unroll
    for (int t = 0; t < 2; t++) {
        int gr0 = rowBase + wr + t * 16 + grp;
        int gr1 = gr0 + 8;
#pragma unroll
        for (int u = 0; u < 8; u++) {
            int gc = colBase + wc + u * 8 + tig * 2;
            if (gr0 < Nrows)
                *reinterpret_cast<float2*>(C + (size_t)gr0 * M + gc) =
                    make_float2(c[t][u][0], c[t][u][1]);
            if (gr1 < Nrows)
                *reinterpret_cast<float2*>(C + (size_t)gr1 * M + gc) =
                    make_float2(c[t][u][2], c[t][u][3]);
        }
    }

    if (HEADS > 0) {
        float ss[2][2] = {{0.f, 0.f}, {0.f, 0.f}};
        float sd[2][2] = {{0.f, 0.f}, {0.f, 0.f}};
#pragma unroll
        for (int u = 0; u < 8; u++) {
            int gc = colBase + wc + u * 8 + tig * 2;
            float2 as = *reinterpret_cast<const float2*>(a_srcv + gc);
            float2 ad = *reinterpret_cast<const float2*>(a_dstv + gc);
#pragma unroll
            for (int t = 0; t < 2; t++) {
                ss[t][0] += c[t][u][0] * as.x + c[t][u][1] * as.y;
                ss[t][1] += c[t][u][2] * as.x + c[t][u][3] * as.y;
                sd[t][0] += c[t][u][0] * ad.x + c[t][u][1] * ad.y;
                sd[t][1] += c[t][u][2] * ad.x + c[t][u][3] * ad.y;
            }
        }
#pragma unroll
        for (int o = 1; o <= 2; o <<= 1) {
#pragma unroll
            for (int t = 0; t < 2; t++)
#pragma unroll
                for (int r = 0; r < 2; r++) {
                    ss[t][r] += __shfl_xor_sync(FULLMASK, ss[t][r], o);
                    sd[t][r] += __shfl_xor_sync(FULLMASK, sd[t][r], o);
                }
        }
        if (tig == 0) {
            int hw = (colBase + wc) >> ((HEADS == 4) ? 6 : 7);
#pragma unroll
            for (int t = 0; t < 2; t++) {
                int r0 = rowBase + wr + t * 16 + grp;
                int r1 = r0 + 8;
                if (HEADS == 4) {
                    if (r0 < Nrows) { esrc[r0 * 4 + hw] = ss[t][0]; edst[r0 * 4 + hw] = sd[t][0]; }
                    if (r1 < Nrows) { esrc[r1 * 4 + hw] = ss[t][1]; edst[r1 * 4 + hw] = sd[t][1]; }
                } else {
                    if (r0 < Nrows) { atomicAdd(&esrc[r0], ss[t][0]); atomicAdd(&edst[r0], sd[t][0]); }
                    if (r1 < Nrows) { atomicAdd(&esrc[r1], ss[t][1]); atomicAdd(&edst[r1], sd[t][1]); }
                }
            }
        }
    }
}

// ---------------- pull aggregation: warp/node + softmax + bias + stats ------
// Nodes assigned via degree-sorted perm -> balanced blocks.
__global__ void pull_stats(const int* __restrict__ off, const int* __restrict__ csr,
                           const int* __restrict__ perm,
                           const float* __restrict__ h,
                           const float* __restrict__ esrc, const float* __restrict__ edst,
                           const float* __restrict__ bias, float* __restrict__ xout,
                           float* __restrict__ gsum, float* __restrict__ gsumsq)
{
    const int H = 4, D = 256, PER = 8;
    __shared__ float sm[PER * 256];

    int w = threadIdx.x >> 5;
    int lane = threadIdx.x & 31;
    int nb = blockIdx.x * 8 + w;
    int n = (nb < NNODES) ? perm[nb] : NNODES;
    const int HH = lane >> 3;           // head owning my channels

    float v[PER];
#pragma unroll
    for (int i = 0; i < PER; i++) v[i] = 0.f;

    if (n < NNODES) {
        int c0 = lane * PER;
        float ed_w = edst[n * H + (lane & 3)];     // dst score for head (lane&3)
        float ed_l = (lane < H) ? ed_w : 0.f;      // lanes 0..3 hold head=lane

        // self loop
        float wl = 0.f;
        if (lane < H) wl = leaky_exp(esrc[n * H + lane] + ed_l);
        float myw = __shfl_sync(FULLMASK, wl, HH);
        float dn = myw;

        float acc[PER];
        {
            const float4* hp = reinterpret_cast<const float4*>(h + (size_t)n * D + c0);
            float4 p = hp[0], q = hp[1];
            acc[0] = myw * p.x; acc[1] = myw * p.y; acc[2] = myw * p.z; acc[3] = myw * p.w;
            acc[4] = myw * q.x; acc[5] = myw * q.y; acc[6] = myw * q.z; acc[7] = myw * q.w;
        }

        int jb = off[n], je = off[n + 1];
        int j = jb;
        for (; j + 3 < je; j += 4) {
            int s0 = csr[j], s1 = csr[j + 1], s2 = csr[j + 2], s3 = csr[j + 3];
            // lanes 0..15: lane = e*4 + hh computes weight of edge e, head hh
            float wle = 0.f;
            if (lane < 16) {
                int e = lane >> 2;
                int se = (e == 0) ? s0 : (e == 1) ? s1 : (e == 2) ? s2 : s3;
                wle = leaky_exp(esrc[se * H + (lane & 3)] + ed_w);
            }
            float w0 = __shfl_sync(FULLMASK, wle, 0 + HH);
            float w1 = __shfl_sync(FULLMASK, wle, 4 + HH);
            float w2 = __shfl_sync(FULLMASK, wle, 8 + HH);
            float w3 = __shfl_sync(FULLMASK, wle, 12 + HH);
            dn += (w0 + w1) + (w2 + w3);

            const float4* hp0 = reinterpret_cast<const float4*>(h + (size_t)s0 * D + c0);
            const float4* hp1 = reinterpret_cast<const float4*>(h + (size_t)s1 * D + c0);
            const float4* hp2 = reinterpret_cast<const float4*>(h + (size_t)s2 * D + c0);
            const float4* hp3 = reinterpret_cast<const float4*>(h + (size_t)s3 * D + c0);
            float4 p0 = hp0[0], q0 = hp0[1];
            float4 p1 = hp1[0], q1 = hp1[1];
            float4 p2 = hp2[0], q2 = hp2[1];
            float4 p3 = hp3[0], q3 = hp3[1];
            acc[0] = fmaf(w0, p0.x, acc[0]); acc[1] = fmaf(w0, p0.y, acc[1]);
            acc[2] = fmaf(w0, p0.z, acc[2]); acc[3] = fmaf(w0, p0.w, acc[3]);
            acc[4] = fmaf(w0, q0.x, acc[4]); acc[5] = fmaf(w0, q0.y, acc[5]);
            acc[6] = fmaf(w0, q0.z, acc[6]); acc[7] = fmaf(w0, q0.w, acc[7]);
            acc[0] = fmaf(w1, p1.x, acc[0]); acc[1] = fmaf(w1, p1.y, acc[1]);
            acc[2] = fmaf(w1, p1.z, acc[2]); acc[3] = fmaf(w1, p1.w, acc[3]);
            acc[4] = fmaf(w1, q1.x, acc[4]); acc[5] = fmaf(w1, q1.y, acc[5]);
            acc[6] = fmaf(w1, q1.z, acc[6]); acc[7] = fmaf(w1, q1.w, acc[7]);
            acc[0] = fmaf(w2, p2.x, acc[0]); acc[1] = fmaf(w2, p2.y, acc[1]);
            acc[2] = fmaf(w2, p2.z, acc[2]); acc[3] = fmaf(w2, p2.w, acc[3]);
            acc[4] = fmaf(w2, q2.x, acc[4]); acc[5] = fmaf(w2, q2.y, acc[5]);
            acc[6] = fmaf(w2, q2.z, acc[6]); acc[7] = fmaf(w2, q2.w, acc[7]);
            acc[0] = fmaf(w3, p3.x, acc[0]); acc[1] = fmaf(w3, p3.y, acc[1]);
            acc[2] = fmaf(w3, p3.z, acc[2]); acc[3] = fmaf(w3, p3.w, acc[3]);
            acc[4] = fmaf(w3, q3.x, acc[4]); acc[5] = fmaf(w3, q3.y, acc[5]);
            acc[6] = fmaf(w3, q3.z, acc[6]); acc[7] = fmaf(w3, q3.w, acc[7]);
        }
        for (; j < je; j++) {
            int s = csr[j];
            float wl2 = 0.f;
            if (lane < H) wl2 = leaky_exp(esrc[s * H + lane] + ed_l);
            float we = __shfl_sync(FULLMASK, wl2, HH);
            dn += we;
            const float4* hp = reinterpret_cast<const float4*>(h + (size_t)s * D + c0);
            float4 p = hp[0], q = hp[1];
            acc[0] = fmaf(we, p.x, acc[0]); acc[1] = fmaf(we, p.y, acc[1]);
            acc[2] = fmaf(we, p.z, acc[2]); acc[3] = fmaf(we, p.w, acc[3]);
            acc[4] = fmaf(we, q.x, acc[4]); acc[5] = fmaf(we, q.y, acc[5]);
            acc[6] = fmaf(we, q.z, acc[6]); acc[7] = fmaf(we, q.w, acc[7]);
        }

        float inv = 1.f / (dn + 1e-16f);
#pragma unroll
        for (int i = 0; i < PER; i++) v[i] = fmaf(acc[i], inv, bias[c0 + i]);

        float4* xp = reinterpret_cast<float4*>(xout + (size_t)n * D + c0);
        xp[0] = make_float4(v[0], v[1], v[2], v[3]);
        xp[1] = make_float4(v[4], v[5], v[6], v[7]);
    }

    // fused per-block stats (conflict-free)
#pragma unroll
    for (int i = 0; i < PER; i++) sm[i * 256 + w * 32 + lane] = v[i];
    __syncthreads();

    int c = threadIdx.x;
    int li = c >> 3, ii = c & 7;
    float s = 0.f, s2 = 0.f;
#pragma unroll
    for (int ww = 0; ww < 8; ww++) {
        float x = sm[ii * 256 + ww * 32 + li];
        s += x;
        s2 += x * x;
    }
    atomicAdd(&gsum[c], s);
    atomicAdd(&gsumsq[c], s2);
}

// ---------------- layer-2 pull + output linear (unrolled x4, perm) ----------
__global__ void pull_out(const int* __restrict__ off, const int* __restrict__ csr,
                         const int* __restrict__ perm,
                         const float* __restrict__ h,
                         const float* __restrict__ esrc, const float* __restrict__ edst,
                         const float* __restrict__ b2, const float* __restrict__ ow,
                         const float* __restrict__ ob, float* __restrict__ out)
{
    const int D = 128;
    int w = threadIdx.x >> 5;
    int lane = threadIdx.x & 31;
    int nb = blockIdx.x * 8 + w;
    if (nb >= NNODES) return;
    int n = perm[nb];
    int c0 = lane * 4;

    float ed_l = edst[n];
    float wself = leaky_exp(esrc[n] + ed_l);
    float dn = wself;

    float acc0, acc1, acc2, acc3;
    {
        float4 p = *reinterpret_cast<const float4*>(h + (size_t)n * D + c0);
        acc0 = wself * p.x; acc1 = wself * p.y; acc2 = wself * p.z; acc3 = wself * p.w;
    }

    int jb = off[n], je = off[n + 1];
    int j = jb;
    for (; j + 3 < je; j += 4) {
        int s0 = csr[j], s1 = csr[j + 1], s2 = csr[j + 2], s3 = csr[j + 3];
        float wle = 0.f;
        if (lane < 4) {
            int se = (lane == 0) ? s0 : (lane == 1) ? s1 : (lane == 2) ? s2 : s3;
            wle = leaky_exp(esrc[se] + ed_l);
        }
        float w0 = __shfl_sync(FULLMASK, wle, 0);
        float w1 = __shfl_sync(FULLMASK, wle, 1);
        float w2 = __shfl_sync(FULLMASK, wle, 2);
        float w3 = __shfl_sync(FULLMASK, wle, 3);
        dn += (w0 + w1) + (w2 + w3);
        float4 p0 = *reinterpret_cast<const float4*>(h + (size_t)s0 * D + c0);
        float4 p1 = *reinterpret_cast<const float4*>(h + (size_t)s1 * D + c0);
        float4 p2 = *reinterpret_cast<const float4*>(h + (size_t)s2 * D + c0);
        float4 p3 = *reinterpret_cast<const float4*>(h + (size_t)s3 * D + c0);
        acc0 = fmaf(w0, p0.x, acc0); acc1 = fmaf(w0, p0.y, acc1);
        acc2 = fmaf(w0, p0.z, acc2); acc3 = fmaf(w0, p0.w, acc3);
        acc0 = fmaf(w1, p1.x, acc0); acc1 = fmaf(w1, p1.y, acc1);
        acc2 = fmaf(w1, p1.z, acc2); acc3 = fmaf(w1, p1.w, acc3);
        acc0 = fmaf(w2, p2.x, acc0); acc1 = fmaf(w2, p2.y, acc1);
        acc2 = fmaf(w2, p2.z, acc2); acc3 = fmaf(w2, p2.w, acc3);
        acc0 = fmaf(w3, p3.x, acc0); acc1 = fmaf(w3, p3.y, acc1);
        acc2 = fmaf(w3, p3.z, acc2); acc3 = fmaf(w3, p3.w, acc3);
    }
    for (; j < je; j++) {
        int s = csr[j];
        float wl2 = (lane == 0) ? leaky_exp(esrc[s] + ed_l) : 0.f;
        float we = __shfl_sync(FULLMASK, wl2, 0);
        dn += we;
        float4 p = *reinterpret_cast<const float4*>(h + (size_t)s * D + c0);
        acc0 = fmaf(we, p.x, acc0); acc1 = fmaf(we, p.y, acc1);
        acc2 = fmaf(we, p.z, acc2); acc3 = fmaf(we, p.w, acc3);
    }

    float inv = 1.f / (dn + 1e-16f);
    float4 bb = *reinterpret_cast<const float4*>(b2 + c0);
    float4 o0 = *reinterpret_cast<const float4*>(ow + c0);
    float4 o1 = *reinterpret_cast<const float4*>(ow + 128 + c0);
    float t0 = fmaf(acc0, inv, bb.x);
    float t1 = fmaf(acc1, inv, bb.y);
    float t2 = fmaf(acc2, inv, bb.z);
    float t3 = fmaf(acc3, inv, bb.w);
    float d0 = t0 * o0.x + t1 * o0.y + t2 * o0.z + t3 * o0.w;
    float d1 = t0 * o1.x + t1 * o1.y + t2 * o1.z + t3 * o1.w;
#pragma unroll
    for (int o = 16; o > 0; o >>= 1) {
        d0 += __shfl_xor_sync(FULLMASK, d0, o);
        d1 += __shfl_xor_sync(FULLMASK, d1, o);
    }
    if (lane == 0) {
        out[n * 2 + 0] = d0 + ob[0];
        out[n * 2 + 1] = d1 + ob[1];
    }
}

// ---------------- norm prep -------------------------------------------------
__global__ void norm_prep(float* __restrict__ gsum, float* __restrict__ gsumsq,
                          const float* __restrict__ gw, const float* __restrict__ gb,
                          const float* __restrict__ ms,
                          float* __restrict__ scale, float* __restrict__ shift)
{
    int c = threadIdx.x;
    const float invN = 1.f / (float)NNODES;
    float mean = gsum[c] * invN;
    float msq = gsumsq[c] * invN;
    float mm = mean * ms[c];
    float var = msq - 2.f * mm * mean + mm * mm;
    float sc = gw[c] * rsqrtf(var + EPS);
    scale[c] = sc;
    shift[c] = gb[c] - sc * mm;
    gsum[c] = 0.f;
    gsumsq[c] = 0.f;
}

// ---------------- launch ----------------------------------------------------
extern "C" void kernel_launch(void* const* d_in, const int* in_sizes, int n_in,
                              void* d_out, int out_size)
{
    const float* x      = (const float*)d_in[0];
    const int*   ei     = (const int*)d_in[1];
    const float* W0     = (const float*)d_in[2];
    const float* a_src0 = (const float*)d_in[3];
    const float* a_dst0 = (const float*)d_in[4];
    const float* b0     = (const float*)d_in[5];
    const float* gnw0   = (const float*)d_in[6];
    const float* gnb0   = (const float*)d_in[7];
    const float* gnms0  = (const float*)d_in[8];
    const float* W1     = (const float*)d_in[9];
    const float* a_src1 = (const float*)d_in[10];
    const float* a_dst1 = (const float*)d_in[11];
    const float* b1     = (const float*)d_in[12];
    const float* gnw1   = (const float*)d_in[13];
    const float* gnb1   = (const float*)d_in[14];
    const float* gnms1  = (const float*)d_in[15];
    const float* W2     = (const float*)d_in[16];
    const float* a_src2 = (const float*)d_in[17];
    const float* a_dst2 = (const float*)d_in[18];
    const float* b2     = (const float*)d_in[19];
    const float* ow     = (const float*)d_in[20];
    const float* ob     = (const float*)d_in[21];

    const int* srcp = ei;
    const int* dstp = ei + NEDGES;
    float* out = (float*)d_out;

    float *ph, *px, *pes, *ped, *pstats;
    int *pdeg, *poff, *ppos, *pcsr, *phist, *phpos, *pperm;
    cudaGetSymbolAddress((void**)&ph, g_h);
    cudaGetSymbolAddress((void**)&px, g_x);
    cudaGetSymbolAddress((void**)&pes, g_esrc);
    cudaGetSymbolAddress((void**)&ped, g_edst);
    cudaGetSymbolAddress((void**)&pstats, g_stats);
    cudaGetSymbolAddress((void**)&pdeg, g_deg);
    cudaGetSymbolAddress((void**)&poff, g_off);
    cudaGetSymbolAddress((void**)&ppos, g_pos);
    cudaGetSymbolAddress((void**)&pcsr, g_csr);
    cudaGetSymbolAddress((void**)&phist, g_hist);
    cudaGetSymbolAddress((void**)&phpos, g_hpos);
    cudaGetSymbolAddress((void**)&pperm, g_perm);
    float* gsum = pstats;
    float* gsumsq = pstats + 256;
    float* scale = pstats + 512;
    float* shift = pstats + 768;

    const int NODE_BLOCKS = (NNODES + 7) / 8;        // 6250
    const int NODE_GRID = (NNODES + 255) / 256;
    const int EDGE_GRID = (NEDGES + 255) / 256;
    const int ROW_TILES = (NNODES + 127) / 128;      // 391
    dim3 gemm_grid0(2, ROW_TILES);                   // M=256
    dim3 gemm_grid2(1, ROW_TILES);                   // M=128

    // ---------- CSR + degree-sorted perm build (once; reused by all layers) ----
    cudaMemsetAsync(pdeg, 0, NNODES * sizeof(int));
    cudaMemsetAsync(phist, 0, 256 * sizeof(int));
    cudaMemsetAsync(pstats, 0, 512 * sizeof(float));
    csr_count<<<EDGE_GRID, 256>>>(dstp, pdeg);
    csr_scan<<<1, 1024>>>(pdeg, poff, ppos);
    deg_hist<<<NODE_GRID, 256>>>(pdeg, phist);
    csr_fill<<<EDGE_GRID, 256>>>(srcp, dstp, ppos, pcsr);
    hist_scan<<<1, 256>>>(phist, phpos);
    perm_fill<<<NODE_GRID, 256>>>(pdeg, phpos, pperm);

    // ---------- layer 0 ----------
    gemm_tf32<0, 4><<<gemm_grid0, 256>>>(x, W0, ph, NNODES, 128, 256,
                                         nullptr, nullptr, a_src0, a_dst0, pes, ped);
    pull_stats<<<NODE_BLOCKS, 256>>>(poff, pcsr, pperm, ph, pes, ped, b0, px, gsum, gsumsq);
    norm_prep<<<1, 256>>>(gsum, gsumsq, gnw0, gnb0, gnms0, scale, shift);

    // ---------- layer 1 ----------
    gemm_tf32<1, 4><<<gemm_grid0, 256>>>(px, W1, ph, NNODES, 256, 256,
                                         scale, shift, a_src1, a_dst1, pes, ped);
    pull_stats<<<NODE_BLOCKS, 256>>>(poff, pcsr, pperm, ph, pes, ped, b1, px, gsum, gsumsq);
    norm_prep<<<1, 256>>>(gsum, gsumsq, gnw1, gnb1, gnms1, scale, shift);

    // ---------- layer 2 ----------
    cudaMemsetAsync(pes, 0, NNODES * sizeof(float));
    cudaMemsetAsync(ped, 0, NNODES * sizeof(float));
    gemm_tf32<1, 1><<<gemm_grid2, 256>>>(px, W2, ph, NNODES, 256, 128,
                                         scale, shift, a_src2, a_dst2, pes, ped);
    pull_out<<<NODE_BLOCKS, 256>>>(poff, pcsr, pperm, ph, pes, ped, b2, ow, ob, out);
}

// round 13
// speedup vs baseline: 1.0078x; 1.0078x over previous
#include <cuda_runtime.h>
#include <cstdint>

// ---------------- problem constants ----------------
#define NNODES 50000
#define NEDGES 400000
#define NEG_SLOPE 0.2f
#define EPS 1e-5f
#define FULLMASK 0xffffffffu

// ---------------- scratch (device globals; no allocs allowed) ----------------
__device__ float g_h  [NNODES * 256];
__device__ float g_x  [NNODES * 256];
__device__ float g_esrc[NNODES * 4];
__device__ float g_edst[NNODES * 4];
__device__ float g_stats[1024];         // [sum|sumsq|scale|shift] x 256
__device__ int   g_deg[NNODES];
__device__ int   g_off[NNODES + 1];
__device__ int   g_pos[NNODES];
__device__ int   g_csr[NEDGES];

// ---------------- helpers ----------------------------------------------------
__device__ __forceinline__ uint32_t f2tf32(float x) {
    uint32_t u;
    asm("cvt.rna.tf32.f32 %0, %1;" : "=r"(u) : "f"(x));
    return u;
}

__device__ __forceinline__ void mma_tf32(float& c0, float& c1, float& c2, float& c3,
                                         uint32_t a0, uint32_t a1, uint32_t a2, uint32_t a3,
                                         uint32_t b0, uint32_t b1) {
    asm volatile(
        "mma.sync.aligned.m16n8k8.row.col.f32.tf32.tf32.f32 "
        "{%0,%1,%2,%3}, {%4,%5,%6,%7}, {%8,%9}, {%0,%1,%2,%3};"
        : "+f"(c0), "+f"(c1), "+f"(c2), "+f"(c3)
        : "r"(a0), "r"(a1), "r"(a2), "r"(a3), "r"(b0), "r"(b1));
}

__device__ __forceinline__ float leaky_exp(float e) {
    e = (e > 0.f) ? e : NEG_SLOPE * e;
    return __expf(e);
}

// ---------------- CSR build --------------------------------------------------
__global__ void csr_count(const int* __restrict__ dst, int* __restrict__ deg)
{
    int e = blockIdx.x * blockDim.x + threadIdx.x;
    if (e < NEDGES) atomicAdd(&deg[dst[e]], 1);
}

__global__ void csr_scan(const int* __restrict__ deg, int* __restrict__ off,
                         int* __restrict__ pos)
{
    const int CHUNK = (NNODES + 1023) / 1024;
    __shared__ int ss[1024];
    int t = threadIdx.x;
    int base = t * CHUNK;
    int s = 0;
    for (int k = 0; k < CHUNK; k++) {
        int i = base + k;
        if (i < NNODES) s += deg[i];
    }
    ss[t] = s;
    __syncthreads();
    for (int o = 1; o < 1024; o <<= 1) {
        int v = (t >= o) ? ss[t - o] : 0;
        __syncthreads();
        ss[t] += v;
        __syncthreads();
    }
    int run = (t > 0) ? ss[t - 1] : 0;
    for (int k = 0; k < CHUNK; k++) {
        int i = base + k;
        if (i < NNODES) {
            off[i] = run;
            pos[i] = run;
            run += deg[i];
        }
    }
    if (t == 1023) off[NNODES] = ss[1023];
}

__global__ void csr_fill(const int* __restrict__ src, const int* __restrict__ dst,
                         int* __restrict__ pos, int* __restrict__ csr)
{
    int e = blockIdx.x * blockDim.x + threadIdx.x;
    if (e < NEDGES) {
        int p = atomicAdd(&pos[dst[e]], 1);
        csr[p] = src[e];
    }
}

// ---------------- tf32 tensor-core GEMM + fused attn-score epilogue ----------
// Fragment-packed smem layout:
//   A: As2[rowpair rp][80], rp = (r>>4)*8 + (r&7), slot s = (r>>3)&1.
//      element (r,k) at As2[rp][(k>>3)*16 + (k&3)*4 + ((k>>2)&1)*2 + s]
//      -> a-fragment (r0,k),(r0+8,k),(r0,k+4),(r0+8,k+4) is one LDS.128.
//   B: Bs2[row][40]; element (r,k) at Bs2[r][(k>>3)*8 + (k&3)*2 + ((k>>2)&1)]
//      -> b-fragment (k),(k+4) is one LDS.64.
template <int NORM, int HEADS>
__global__ void gemm_tf32(const float* __restrict__ X, const float* __restrict__ W,
                          float* __restrict__ C, int Nrows, int K, int M,
                          const float* __restrict__ scale, const float* __restrict__ shift,
                          const float* __restrict__ a_srcv, const float* __restrict__ a_dstv,
                          float* __restrict__ esrc, float* __restrict__ edst)
{
    __shared__ float As2[64][80];    // 20 KB
    __shared__ float Bs2[128][40];   // 20 KB

    const int tid = threadIdx.x;
    const int rowBase = blockIdx.y * 128;
    const int colBase = blockIdx.x * 128;
    const int warp = tid >> 5;
    const int lane = tid & 31;
    const int wr = (warp & 3) * 32;
    const int wc = (warp >> 2) * 64;
    const int grp = lane >> 2;
    const int tig = lane & 3;

    float c[2][8][4];
#pragma unroll
    for (int t = 0; t < 2; t++)
#pragma unroll
        for (int u = 0; u < 8; u++)
#pragma unroll
            for (int v = 0; v < 4; v++) c[t][u][v] = 0.f;

    const int rpb = (warp & 3) * 16 + grp;   // rowpair base for this thread

    for (int k0 = 0; k0 < K; k0 += 32) {
        // load A tile (fragment-packed scatter)
#pragma unroll
        for (int l = 0; l < 4; l++) {
            int idx = tid + l * 256;
            int r = idx >> 3;
            int kk = (idx & 7) * 4;
            int gr = rowBase + r;
            float4 v = make_float4(0.f, 0.f, 0.f, 0.f);
            if (gr < Nrows)
                v = *reinterpret_cast<const float4*>(X + (size_t)gr * K + k0 + kk);
            if (NORM) {
                float4 sc = *reinterpret_cast<const float4*>(scale + k0 + kk);
                float4 sh = *reinterpret_cast<const float4*>(shift + k0 + kk);
                v.x = fmaxf(fmaf(sc.x, v.x, sh.x), 0.f);
                v.y = fmaxf(fmaf(sc.y, v.y, sh.y), 0.f);
                v.z = fmaxf(fmaf(sc.z, v.z, sh.z), 0.f);
                v.w = fmaxf(fmaf(sc.w, v.w, sh.w), 0.f);
            }
            int rp = ((r >> 4) << 3) + (r & 7);
            int s = (r >> 3) & 1;
            int base = (kk >> 3) * 16 + ((kk >> 2) & 1) * 2 + s;
            As2[rp][base + 0]  = __uint_as_float(f2tf32(v.x));
            As2[rp][base + 4]  = __uint_as_float(f2tf32(v.y));
            As2[rp][base + 8]  = __uint_as_float(f2tf32(v.z));
            As2[rp][base + 12] = __uint_as_float(f2tf32(v.w));
        }
        // load B tile (fragment-packed scatter)
#pragma unroll
        for (int l = 0; l < 4; l++) {
            int idx = tid + l * 256;
            int r = idx >> 3;
            int kk = (idx & 7) * 4;
            float4 v = *reinterpret_cast<const float4*>(W + (size_t)(colBase + r) * K + k0 + kk);
            int base = (kk >> 3) * 8 + ((kk >> 2) & 1);
            Bs2[r][base + 0] = __uint_as_float(f2tf32(v.x));
            Bs2[r][base + 2] = __uint_as_float(f2tf32(v.y));
            Bs2[r][base + 4] = __uint_as_float(f2tf32(v.z));
            Bs2[r][base + 6] = __uint_as_float(f2tf32(v.w));
        }
        __syncthreads();

#pragma unroll
        for (int kkg = 0; kkg < 4; kkg++) {
            float4 af[2];
            af[0] = *reinterpret_cast<const float4*>(&As2[rpb][kkg * 16 + tig * 4]);
            af[1] = *reinterpret_cast<const float4*>(&As2[rpb + 8][kkg * 16 + tig * 4]);
            float2 bf[8];
#pragma unroll
            for (int u = 0; u < 8; u++)
                bf[u] = *reinterpret_cast<const float2*>(&Bs2[wc + u * 8 + grp][kkg * 8 + tig * 2]);
#pragma unroll
            for (int t = 0; t < 2; t++)
#pragma unroll
                for (int u = 0; u < 8; u++)
                    mma_tf32(c[t][u][0], c[t][u][1], c[t][u][2], c[t][u][3],
                             __float_as_uint(af[t].x), __float_as_uint(af[t].y),
                             __float_as_uint(af[t].z), __float_as_uint(af[t].w),
                             __float_as_uint(bf[u].x), __float_as_uint(bf[u].y));
        }
        __syncthreads();
    }

    // store C
#pragma unroll
    for (int t = 0; t < 2; t++) {
        int gr0 = rowBase + wr + t * 16 + grp;
        int gr1 = gr0 + 8;
#pragma unroll
        for (int u = 0; u < 8; u++) {
            int gc = colBase + wc + u * 8 + tig * 2;
            if (gr0 < Nrows)
                *reinterpret_cast<float2*>(C + (size_t)gr0 * M + gc) =
                    make_float2(c[t][u][0], c[t][u][1]);
            if (gr1 < Nrows)
                *reinterpret_cast<float2*>(C + (size_t)gr1 * M + gc) =
                    make_float2(c[t][u][2], c[t][u][3]);
        }
    }

    // fused attention-score epilogue
    if (HEADS > 0) {
        float ss[2][2] = {{0.f, 0.f}, {0.f, 0.f}};
        float sd[2][2] = {{0.f, 0.f}, {0.f, 0.f}};
#pragma unroll
        for (int u = 0; u < 8; u++) {
            int gc = colBase + wc + u * 8 + tig * 2;
            float2 as = *reinterpret_cast<const float2*>(a_srcv + gc);
            float2 ad = *reinterpret_cast<const float2*>(a_dstv + gc);
#pragma unroll
            for (int t = 0; t < 2; t++) {
                ss[t][0] += c[t][u][0] * as.x + c[t][u][1] * as.y;
                ss[t][1] += c[t][u][2] * as.x + c[t][u][3] * as.y;
                sd[t][0] += c[t][u][0] * ad.x + c[t][u][1] * ad.y;
                sd[t][1] += c[t][u][2] * ad.x + c[t][u][3] * ad.y;
            }
        }
#pragma unroll
        for (int o = 1; o <= 2; o <<= 1) {
#pragma unroll
            for (int t = 0; t < 2; t++)
#pragma unroll
                for (int r = 0; r < 2; r++) {
                    ss[t][r] += __shfl_xor_sync(FULLMASK, ss[t][r], o);
                    sd[t][r] += __shfl_xor_sync(FULLMASK, sd[t][r], o);
                }
        }
        if (tig == 0) {
            int hw = (colBase + wc) >> ((HEADS == 4) ? 6 : 7);
#pragma unroll
            for (int t = 0; t < 2; t++) {
                int r0 = rowBase + wr + t * 16 + grp;
                int r1 = r0 + 8;
                if (HEADS == 4) {
                    if (r0 < Nrows) { esrc[r0 * 4 + hw] = ss[t][0]; edst[r0 * 4 + hw] = sd[t][0]; }
                    if (r1 < Nrows) { esrc[r1 * 4 + hw] = ss[t][1]; edst[r1 * 4 + hw] = sd[t][1]; }
                } else {
                    if (r0 < Nrows) { atomicAdd(&esrc[r0], ss[t][0]); atomicAdd(&edst[r0], sd[t][0]); }
                    if (r1 < Nrows) { atomicAdd(&esrc[r1], ss[t][1]); atomicAdd(&edst[r1], sd[t][1]); }
                }
            }
        }
    }
}

// ---------------- pull aggregation: warp/node + softmax + bias + stats ------
__global__ void pull_stats(const int* __restrict__ off, const int* __restrict__ csr,
                           const float* __restrict__ h,
                           const float* __restrict__ esrc, const float* __restrict__ edst,
                           const float* __restrict__ bias, float* __restrict__ xout,
                           float* __restrict__ gsum, float* __restrict__ gsumsq)
{
    const int H = 4, D = 256, PER = 8;
    __shared__ float sm[PER * 256];

    int w = threadIdx.x >> 5;
    int lane = threadIdx.x & 31;
    int n = blockIdx.x * 8 + w;
    const int HH = lane >> 3;           // head owning my channels

    float v[PER];
#pragma unroll
    for (int i = 0; i < PER; i++) v[i] = 0.f;

    if (n < NNODES) {
        int c0 = lane * PER;
        float ed_w = edst[n * H + (lane & 3)];     // dst score for head (lane&3)
        float ed_l = (lane < H) ? ed_w : 0.f;

        // self loop
        float wl = 0.f;
        if (lane < H) wl = leaky_exp(esrc[n * H + lane] + ed_l);
        float myw = __shfl_sync(FULLMASK, wl, HH);
        float dn = myw;

        float acc[PER];
        {
            const float4* hp = reinterpret_cast<const float4*>(h + (size_t)n * D + c0);
            float4 p = hp[0], q = hp[1];
            acc[0] = myw * p.x; acc[1] = myw * p.y; acc[2] = myw * p.z; acc[3] = myw * p.w;
            acc[4] = myw * q.x; acc[5] = myw * q.y; acc[6] = myw * q.z; acc[7] = myw * q.w;
        }

        int jb = off[n], je = off[n + 1];
        int j = jb;
        for (; j + 3 < je; j += 4) {
            int s0 = csr[j], s1 = csr[j + 1], s2 = csr[j + 2], s3 = csr[j + 3];
            float wle = 0.f;
            if (lane < 16) {
                int e = lane >> 2;
                int se = (e == 0) ? s0 : (e == 1) ? s1 : (e == 2) ? s2 : s3;
                wle = leaky_exp(esrc[se * H + (lane & 3)] + ed_w);
            }
            float w0 = __shfl_sync(FULLMASK, wle, 0 + HH);
            float w1 = __shfl_sync(FULLMASK, wle, 4 + HH);
            float w2 = __shfl_sync(FULLMASK, wle, 8 + HH);
            float w3 = __shfl_sync(FULLMASK, wle, 12 + HH);
            dn += (w0 + w1) + (w2 + w3);

            const float4* hp0 = reinterpret_cast<const float4*>(h + (size_t)s0 * D + c0);
            const float4* hp1 = reinterpret_cast<const float4*>(h + (size_t)s1 * D + c0);
            const float4* hp2 = reinterpret_cast<const float4*>(h + (size_t)s2 * D + c0);
            const float4* hp3 = reinterpret_cast<const float4*>(h + (size_t)s3 * D + c0);
            float4 p0 = hp0[0], q0 = hp0[1];
            float4 p1 = hp1[0], q1 = hp1[1];
            float4 p2 = hp2[0], q2 = hp2[1];
            float4 p3 = hp3[0], q3 = hp3[1];
            acc[0] = fmaf(w0, p0.x, acc[0]); acc[1] = fmaf(w0, p0.y, acc[1]);
            acc[2] = fmaf(w0, p0.z, acc[2]); acc[3] = fmaf(w0, p0.w, acc[3]);
            acc[4] = fmaf(w0, q0.x, acc[4]); acc[5] = fmaf(w0, q0.y, acc[5]);
            acc[6] = fmaf(w0, q0.z, acc[6]); acc[7] = fmaf(w0, q0.w, acc[7]);
            acc[0] = fmaf(w1, p1.x, acc[0]); acc[1] = fmaf(w1, p1.y, acc[1]);
            acc[2] = fmaf(w1, p1.z, acc[2]); acc[3] = fmaf(w1, p1.w, acc[3]);
            acc[4] = fmaf(w1, q1.x, acc[4]); acc[5] = fmaf(w1, q1.y, acc[5]);
            acc[6] = fmaf(w1, q1.z, acc[6]); acc[7] = fmaf(w1, q1.w, acc[7]);
            acc[0] = fmaf(w2, p2.x, acc[0]); acc[1] = fmaf(w2, p2.y, acc[1]);
            acc[2] = fmaf(w2, p2.z, acc[2]); acc[3] = fmaf(w2, p2.w, acc[3]);
            acc[4] = fmaf(w2, q2.x, acc[4]); acc[5] = fmaf(w2, q2.y, acc[5]);
            acc[6] = fmaf(w2, q2.z, acc[6]); acc[7] = fmaf(w2, q2.w, acc[7]);
            acc[0] = fmaf(w3, p3.x, acc[0]); acc[1] = fmaf(w3, p3.y, acc[1]);
            acc[2] = fmaf(w3, p3.z, acc[2]); acc[3] = fmaf(w3, p3.w, acc[3]);
            acc[4] = fmaf(w3, q3.x, acc[4]); acc[5] = fmaf(w3, q3.y, acc[5]);
            acc[6] = fmaf(w3, q3.z, acc[6]); acc[7] = fmaf(w3, q3.w, acc[7]);
        }
        for (; j < je; j++) {
            int s = csr[j];
            float wl2 = 0.f;
            if (lane < H) wl2 = leaky_exp(esrc[s * H + lane] + ed_l);
            float we = __shfl_sync(FULLMASK, wl2, HH);
            dn += we;
            const float4* hp = reinterpret_cast<const float4*>(h + (size_t)s * D + c0);
            float4 p = hp[0], q = hp[1];
            acc[0] = fmaf(we, p.x, acc[0]); acc[1] = fmaf(we, p.y, acc[1]);
            acc[2] = fmaf(we, p.z, acc[2]); acc[3] = fmaf(we, p.w, acc[3]);
            acc[4] = fmaf(we, q.x, acc[4]); acc[5] = fmaf(we, q.y, acc[5]);
            acc[6] = fmaf(we, q.z, acc[6]); acc[7] = fmaf(we, q.w, acc[7]);
        }

        float inv = 1.f / (dn + 1e-16f);
#pragma unroll
        for (int i = 0; i < PER; i++) v[i] = fmaf(acc[i], inv, bias[c0 + i]);

        float4* xp = reinterpret_cast<float4*>(xout + (size_t)n * D + c0);
        xp[0] = make_float4(v[0], v[1], v[2], v[3]);
        xp[1] = make_float4(v[4], v[5], v[6], v[7]);
    }

    // fused per-block stats (conflict-free)
#pragma unroll
    for (int i = 0; i < PER; i++) sm[i * 256 + w * 32 + lane] = v[i];
    __syncthreads();

    int c = threadIdx.x;
    int li = c >> 3, ii = c & 7;
    float s = 0.f, s2 = 0.f;
#pragma unroll
    for (int ww = 0; ww < 8; ww++) {
        float x = sm[ii * 256 + ww * 32 + li];
        s += x;
        s2 += x * x;
    }
    atomicAdd(&gsum[c], s);
    atomicAdd(&gsumsq[c], s2);
}

// ---------------- layer-2 pull + output linear (unrolled x4) ----------------
__global__ void pull_out(const int* __restrict__ off, const int* __restrict__ csr,
                         const float* __restrict__ h,
                         const float* __restrict__ esrc, const float* __restrict__ edst,
                         const float* __restrict__ b2, const float* __restrict__ ow,
                         const float* __restrict__ ob, float* __restrict__ out)
{
    const int D = 128;
    int w = threadIdx.x >> 5;
    int lane = threadIdx.x & 31;
    int n = blockIdx.x * 8 + w;
    if (n >= NNODES) return;
    int c0 = lane * 4;

    float ed_l = edst[n];
    float wself = leaky_exp(esrc[n] + ed_l);
    float dn = wself;

    float acc0, acc1, acc2, acc3;
    {
        float4 p = *reinterpret_cast<const float4*>(h + (size_t)n * D + c0);
        acc0 = wself * p.x; acc1 = wself * p.y; acc2 = wself * p.z; acc3 = wself * p.w;
    }

    int jb = off[n], je = off[n + 1];
    int j = jb;
    for (; j + 3 < je; j += 4) {
        int s0 = csr[j], s1 = csr[j + 1], s2 = csr[j + 2], s3 = csr[j + 3];
        float wle = 0.f;
        if (lane < 4) {
            int se = (lane == 0) ? s0 : (lane == 1) ? s1 : (lane == 2) ? s2 : s3;
            wle = leaky_exp(esrc[se] + ed_l);
        }
        float w0 = __shfl_sync(FULLMASK, wle, 0);
        float w1 = __shfl_sync(FULLMASK, wle, 1);
        float w2 = __shfl_sync(FULLMASK, wle, 2);
        float w3 = __shfl_sync(FULLMASK, wle, 3);
        dn += (w0 + w1) + (w2 + w3);
        float4 p0 = *reinterpret_cast<const float4*>(h + (size_t)s0 * D + c0);
        float4 p1 = *reinterpret_cast<const float4*>(h + (size_t)s1 * D + c0);
        float4 p2 = *reinterpret_cast<const float4*>(h + (size_t)s2 * D + c0);
        float4 p3 = *reinterpret_cast<const float4*>(h + (size_t)s3 * D + c0);
        acc0 = fmaf(w0, p0.x, acc0); acc1 = fmaf(w0, p0.y, acc1);
        acc2 = fmaf(w0, p0.z, acc2); acc3 = fmaf(w0, p0.w, acc3);
        acc0 = fmaf(w1, p1.x, acc0); acc1 = fmaf(w1, p1.y, acc1);
        acc2 = fmaf(w1, p1.z, acc2); acc3 = fmaf(w1, p1.w, acc3);
        acc0 = fmaf(w2, p2.x, acc0); acc1 = fmaf(w2, p2.y, acc1);
        acc2 = fmaf(w2, p2.z, acc2); acc3 = fmaf(w2, p2.w, acc3);
        acc0 = fmaf(w3, p3.x, acc0); acc1 = fmaf(w3, p3.y, acc1);
        acc2 = fmaf(w3, p3.z, acc2); acc3 = fmaf(w3, p3.w, acc3);
    }
    for (; j < je; j++) {
        int s = csr[j];
        float wl2 = (lane == 0) ? leaky_exp(esrc[s] + ed_l) : 0.f;
        float we = __shfl_sync(FULLMASK, wl2, 0);
        dn += we;
        float4 p = *reinterpret_cast<const float4*>(h + (size_t)s * D + c0);
        acc0 = fmaf(we, p.x, acc0); acc1 = fmaf(we, p.y, acc1);
        acc2 = fmaf(we, p.z, acc2); acc3 = fmaf(we, p.w, acc3);
    }

    float inv = 1.f / (dn + 1e-16f);
    float4 bb = *reinterpret_cast<const float4*>(b2 + c0);
    float4 o0 = *reinterpret_cast<const float4*>(ow + c0);
    float4 o1 = *reinterpret_cast<const float4*>(ow + 128 + c0);
    float t0 = fmaf(acc0, inv, bb.x);
    float t1 = fmaf(acc1, inv, bb.y);
    float t2 = fmaf(acc2, inv, bb.z);
    float t3 = fmaf(acc3, inv, bb.w);
    float d0 = t0 * o0.x + t1 * o0.y + t2 * o0.z + t3 * o0.w;
    float d1 = t0 * o1.x + t1 * o1.y + t2 * o1.z + t3 * o1.w;
#pragma unroll
    for (int o = 16; o > 0; o >>= 1) {
        d0 += __shfl_xor_sync(FULLMASK, d0, o);
        d1 += __shfl_xor_sync(FULLMASK, d1, o);
    }
    if (lane == 0) {
        out[n * 2 + 0] = d0 + ob[0];
        out[n * 2 + 1] = d1 + ob[1];
    }
}

// ---------------- norm prep -------------------------------------------------
__global__ void norm_prep(float* __restrict__ gsum, float* __restrict__ gsumsq,
                          const float* __restrict__ gw, const float* __restrict__ gb,
                          const float* __restrict__ ms,
                          float* __restrict__ scale, float* __restrict__ shift)
{
    int c = threadIdx.x;
    const float invN = 1.f / (float)NNODES;
    float mean = gsum[c] * invN;
    float msq = gsumsq[c] * invN;
    float mm = mean * ms[c];
    float var = msq - 2.f * mm * mean + mm * mm;
    float sc = gw[c] * rsqrtf(var + EPS);
    scale[c] = sc;
    shift[c] = gb[c] - sc * mm;
    gsum[c] = 0.f;
    gsumsq[c] = 0.f;
}

// ---------------- launch ----------------------------------------------------
extern "C" void kernel_launch(void* const* d_in, const int* in_sizes, int n_in,
                              void* d_out, int out_size)
{
    const float* x      = (const float*)d_in[0];
    const int*   ei     = (const int*)d_in[1];
    const float* W0     = (const float*)d_in[2];
    const float* a_src0 = (const float*)d_in[3];
    const float* a_dst0 = (const float*)d_in[4];
    const float* b0     = (const float*)d_in[5];
    const float* gnw0   = (const float*)d_in[6];
    const float* gnb0   = (const float*)d_in[7];
    const float* gnms0  = (const float*)d_in[8];
    const float* W1     = (const float*)d_in[9];
    const float* a_src1 = (const float*)d_in[10];
    const float* a_dst1 = (const float*)d_in[11];
    const float* b1     = (const float*)d_in[12];
    const float* gnw1   = (const float*)d_in[13];
    const float* gnb1   = (const float*)d_in[14];
    const float* gnms1  = (const float*)d_in[15];
    const float* W2     = (const float*)d_in[16];
    const float* a_src2 = (const float*)d_in[17];
    const float* a_dst2 = (const float*)d_in[18];
    const float* b2     = (const float*)d_in[19];
    const float* ow     = (const float*)d_in[20];
    const float* ob     = (const float*)d_in[21];

    const int* srcp = ei;
    const int* dstp = ei + NEDGES;
    float* out = (float*)d_out;

    float *ph, *px, *pes, *ped, *pstats;
    int *pdeg, *poff, *ppos, *pcsr;
    cudaGetSymbolAddress((void**)&ph, g_h);
    cudaGetSymbolAddress((void**)&px, g_x);
    cudaGetSymbolAddress((void**)&pes, g_esrc);
    cudaGetSymbolAddress((void**)&ped, g_edst);
    cudaGetSymbolAddress((void**)&pstats, g_stats);
    cudaGetSymbolAddress((void**)&pdeg, g_deg);
    cudaGetSymbolAddress((void**)&poff, g_off);
    cudaGetSymbolAddress((void**)&ppos, g_pos);
    cudaGetSymbolAddress((void**)&pcsr, g_csr);
    float* gsum = pstats;
    float* gsumsq = pstats + 256;
    float* scale = pstats + 512;
    float* shift = pstats + 768;

    const int NODE_BLOCKS = (NNODES + 7) / 8;        // 6250
    const int EDGE_GRID = (NEDGES + 255) / 256;
    const int ROW_TILES = (NNODES + 127) / 128;      // 391
    dim3 gemm_grid0(2, ROW_TILES);                   // M=256
    dim3 gemm_grid2(1, ROW_TILES);                   // M=128

    // ---------- CSR build (once; reused by all 3 layers) ----------
    cudaMemsetAsync(pdeg, 0, NNODES * sizeof(int));
    cudaMemsetAsync(pstats, 0, 512 * sizeof(float));
    csr_count<<<EDGE_GRID, 256>>>(dstp, pdeg);
    csr_scan<<<1, 1024>>>(pdeg, poff, ppos);
    csr_fill<<<EDGE_GRID, 256>>>(srcp, dstp, ppos, pcsr);

    // ---------- layer 0 ----------
    gemm_tf32<0, 4><<<gemm_grid0, 256>>>(x, W0, ph, NNODES, 128, 256,
                                         nullptr, nullptr, a_src0, a_dst0, pes, ped);
    pull_stats<<<NODE_BLOCKS, 256>>>(poff, pcsr, ph, pes, ped, b0, px, gsum, gsumsq);
    norm_prep<<<1, 256>>>(gsum, gsumsq, gnw0, gnb0, gnms0, scale, shift);

    // ---------- layer 1 ----------
    gemm_tf32<1, 4><<<gemm_grid0, 256>>>(px, W1, ph, NNODES, 256, 256,
                                         scale, shift, a_src1, a_dst1, pes, ped);
    pull_stats<<<NODE_BLOCKS, 256>>>(poff, pcsr, ph, pes, ped, b1, px, gsum, gsumsq);
    norm_prep<<<1, 256>>>(gsum, gsumsq, gnw1, gnb1, gnms1, scale, shift);

    // ---------- layer 2 ----------
    cudaMemsetAsync(pes, 0, NNODES * sizeof(float));
    cudaMemsetAsync(ped, 0, NNODES * sizeof(float));
    gemm_tf32<1, 1><<<gemm_grid2, 256>>>(px, W2, ph, NNODES, 256, 128,
                                         scale, shift, a_src2, a_dst2, pes, ped);
    pull_out<<<NODE_BLOCKS, 256>>>(poff, pcsr, ph, pes, ped, b2, ow, ob, out);
}

// round 14
// speedup vs baseline: 1.0712x; 1.0629x over previous
#include <cuda_runtime.h>
#include <cstdint>

// ---------------- problem constants ----------------
#define NNODES 50000
#define NEDGES 400000
#define NEG_SLOPE 0.2f
#define EPS 1e-5f
#define FULLMASK 0xffffffffu

// ---------------- scratch (device globals; no allocs allowed) ----------------
__device__ float g_h  [NNODES * 256];
__device__ float g_x  [NNODES * 256];
__device__ float g_esrc[NNODES * 4];
__device__ float g_edst[NNODES * 4];
__device__ float g_stats[1024];         // [sum|sumsq|scale|shift] x 256
__device__ int   g_deg[NNODES];
__device__ int   g_off[NNODES + 1];
__device__ int   g_pos[NNODES];
__device__ int   g_csr[NEDGES];

// ---------------- helpers ----------------------------------------------------
__device__ __forceinline__ uint32_t f2tf32(float x) {
    uint32_t u;
    asm("cvt.rna.tf32.f32 %0, %1;" : "=r"(u) : "f"(x));
    return u;
}

__device__ __forceinline__ void mma_tf32(float& c0, float& c1, float& c2, float& c3,
                                         uint32_t a0, uint32_t a1, uint32_t a2, uint32_t a3,
                                         uint32_t b0, uint32_t b1) {
    asm volatile(
        "mma.sync.aligned.m16n8k8.row.col.f32.tf32.tf32.f32 "
        "{%0,%1,%2,%3}, {%4,%5,%6,%7}, {%8,%9}, {%0,%1,%2,%3};"
        : "+f"(c0), "+f"(c1), "+f"(c2), "+f"(c3)
        : "r"(a0), "r"(a1), "r"(a2), "r"(a3), "r"(b0), "r"(b1));
}

__device__ __forceinline__ float leaky_exp(float e) {
    e = (e > 0.f) ? e : NEG_SLOPE * e;
    return __expf(e);
}

// ---------------- CSR build --------------------------------------------------
__global__ void csr_count(const int* __restrict__ dst, int* __restrict__ deg)
{
    int e = blockIdx.x * blockDim.x + threadIdx.x;
    if (e < NEDGES) atomicAdd(&deg[dst[e]], 1);
}

__global__ void csr_scan(const int* __restrict__ deg, int* __restrict__ off,
                         int* __restrict__ pos)
{
    const int CHUNK = (NNODES + 1023) / 1024;
    __shared__ int ss[1024];
    int t = threadIdx.x;
    int base = t * CHUNK;
    int s = 0;
    for (int k = 0; k < CHUNK; k++) {
        int i = base + k;
        if (i < NNODES) s += deg[i];
    }
    ss[t] = s;
    __syncthreads();
    for (int o = 1; o < 1024; o <<= 1) {
        int v = (t >= o) ? ss[t - o] : 0;
        __syncthreads();
        ss[t] += v;
        __syncthreads();
    }
    int run = (t > 0) ? ss[t - 1] : 0;
    for (int k = 0; k < CHUNK; k++) {
        int i = base + k;
        if (i < NNODES) {
            off[i] = run;
            pos[i] = run;
            run += deg[i];
        }
    }
    if (t == 1023) off[NNODES] = ss[1023];
}

__global__ void csr_fill(const int* __restrict__ src, const int* __restrict__ dst,
                         int* __restrict__ pos, int* __restrict__ csr)
{
    int e = blockIdx.x * blockDim.x + threadIdx.x;
    if (e < NEDGES) {
        int p = atomicAdd(&pos[dst[e]], 1);
        csr[p] = src[e];
    }
}

// ---------------- tf32 tensor-core GEMM + fused attn-score epilogue ----------
// R7 layout; smem fills vectorized to STS.128 (row pitch 36 floats = 144 B,
// 16B-aligned at kk%4==0 -> legal float4 stores, conflict-free phases).
template <int NORM, int HEADS>
__global__ void gemm_tf32(const float* __restrict__ X, const float* __restrict__ W,
                          float* __restrict__ C, int Nrows, int K, int M,
                          const float* __restrict__ scale, const float* __restrict__ shift,
                          const float* __restrict__ a_srcv, const float* __restrict__ a_dstv,
                          float* __restrict__ esrc, float* __restrict__ edst)
{
    __shared__ float As[128][36];
    __shared__ float Bs[128][36];

    const int tid = threadIdx.x;
    const int rowBase = blockIdx.y * 128;
    const int colBase = blockIdx.x * 128;
    const int warp = tid >> 5;
    const int lane = tid & 31;
    const int wr = (warp & 3) * 32;
    const int wc = (warp >> 2) * 64;
    const int grp = lane >> 2;
    const int tig = lane & 3;

    float c[2][8][4];
#pragma unroll
    for (int t = 0; t < 2; t++)
#pragma unroll
        for (int u = 0; u < 8; u++)
#pragma unroll
            for (int v = 0; v < 4; v++) c[t][u][v] = 0.f;

    for (int k0 = 0; k0 < K; k0 += 32) {
#pragma unroll
        for (int l = 0; l < 4; l++) {
            int idx = tid + l * 256;
            int r = idx >> 3;
            int kk = (idx & 7) * 4;
            int gr = rowBase + r;
            float4 v = make_float4(0.f, 0.f, 0.f, 0.f);
            if (gr < Nrows)
                v = *reinterpret_cast<const float4*>(X + (size_t)gr * K + k0 + kk);
            if (NORM) {
                float4 sc = *reinterpret_cast<const float4*>(scale + k0 + kk);
                float4 sh = *reinterpret_cast<const float4*>(shift + k0 + kk);
                v.x = fmaxf(fmaf(sc.x, v.x, sh.x), 0.f);
                v.y = fmaxf(fmaf(sc.y, v.y, sh.y), 0.f);
                v.z = fmaxf(fmaf(sc.z, v.z, sh.z), 0.f);
                v.w = fmaxf(fmaf(sc.w, v.w, sh.w), 0.f);
            }
            float4 sv;
            sv.x = __uint_as_float(f2tf32(v.x));
            sv.y = __uint_as_float(f2tf32(v.y));
            sv.z = __uint_as_float(f2tf32(v.z));
            sv.w = __uint_as_float(f2tf32(v.w));
            *reinterpret_cast<float4*>(&As[r][kk]) = sv;    // STS.128
        }
#pragma unroll
        for (int l = 0; l < 4; l++) {
            int idx = tid + l * 256;
            int r = idx >> 3;
            int kk = (idx & 7) * 4;
            float4 v = *reinterpret_cast<const float4*>(W + (size_t)(colBase + r) * K + k0 + kk);
            float4 sv;
            sv.x = __uint_as_float(f2tf32(v.x));
            sv.y = __uint_as_float(f2tf32(v.y));
            sv.z = __uint_as_float(f2tf32(v.z));
            sv.w = __uint_as_float(f2tf32(v.w));
            *reinterpret_cast<float4*>(&Bs[r][kk]) = sv;    // STS.128
        }
        __syncthreads();

#pragma unroll
        for (int kk = 0; kk < 32; kk += 8) {
            uint32_t a[2][4];
#pragma unroll
            for (int t = 0; t < 2; t++) {
                int r0 = wr + t * 16 + grp;
                a[t][0] = __float_as_uint(As[r0][kk + tig]);
                a[t][1] = __float_as_uint(As[r0 + 8][kk + tig]);
                a[t][2] = __float_as_uint(As[r0][kk + tig + 4]);
                a[t][3] = __float_as_uint(As[r0 + 8][kk + tig + 4]);
            }
            uint32_t b[8][2];
#pragma unroll
            for (int u = 0; u < 8; u++) {
                int cB = wc + u * 8 + grp;
                b[u][0] = __float_as_uint(Bs[cB][kk + tig]);
                b[u][1] = __float_as_uint(Bs[cB][kk + tig + 4]);
            }
#pragma unroll
            for (int t = 0; t < 2; t++)
#pragma unroll
                for (int u = 0; u < 8; u++)
                    mma_tf32(c[t][u][0], c[t][u][1], c[t][u][2], c[t][u][3],
                             a[t][0], a[t][1], a[t][2], a[t][3], b[u][0], b[u][1]);
        }
        __syncthreads();
    }

    // store C
#pragma unroll
    for (int t = 0; t < 2; t++) {
        int gr0 = rowBase + wr + t * 16 + grp;
        int gr1 = gr0 + 8;
#pragma unroll
        for (int u = 0; u < 8; u++) {
            int gc = colBase + wc + u * 8 + tig * 2;
            if (gr0 < Nrows)
                *reinterpret_cast<float2*>(C + (size_t)gr0 * M + gc) =
                    make_float2(c[t][u][0], c[t][u][1]);
            if (gr1 < Nrows)
                *reinterpret_cast<float2*>(C + (size_t)gr1 * M + gc) =
                    make_float2(c[t][u][2], c[t][u][3]);
        }
    }

    // fused attention-score epilogue
    if (HEADS > 0) {
        float ss[2][2] = {{0.f, 0.f}, {0.f, 0.f}};
        float sd[2][2] = {{0.f, 0.f}, {0.f, 0.f}};
#pragma unroll
        for (int u = 0; u < 8; u++) {
            int gc = colBase + wc + u * 8 + tig * 2;
            float2 as = *reinterpret_cast<const float2*>(a_srcv + gc);
            float2 ad = *reinterpret_cast<const float2*>(a_dstv + gc);
#pragma unroll
            for (int t = 0; t < 2; t++) {
                ss[t][0] += c[t][u][0] * as.x + c[t][u][1] * as.y;
                ss[t][1] += c[t][u][2] * as.x + c[t][u][3] * as.y;
                sd[t][0] += c[t][u][0] * ad.x + c[t][u][1] * ad.y;
                sd[t][1] += c[t][u][2] * ad.x + c[t][u][3] * ad.y;
            }
        }
#pragma unroll
        for (int o = 1; o <= 2; o <<= 1) {
#pragma unroll
            for (int t = 0; t < 2; t++)
#pragma unroll
                for (int r = 0; r < 2; r++) {
                    ss[t][r] += __shfl_xor_sync(FULLMASK, ss[t][r], o);
                    sd[t][r] += __shfl_xor_sync(FULLMASK, sd[t][r], o);
                }
        }
        if (tig == 0) {
            int hw = (colBase + wc) >> ((HEADS == 4) ? 6 : 7);
#pragma unroll
            for (int t = 0; t < 2; t++) {
                int r0 = rowBase + wr + t * 16 + grp;
                int r1 = r0 + 8;
                if (HEADS == 4) {
                    if (r0 < Nrows) { esrc[r0 * 4 + hw] = ss[t][0]; edst[r0 * 4 + hw] = sd[t][0]; }
                    if (r1 < Nrows) { esrc[r1 * 4 + hw] = ss[t][1]; edst[r1 * 4 + hw] = sd[t][1]; }
                } else {
                    if (r0 < Nrows) { atomicAdd(&esrc[r0], ss[t][0]); atomicAdd(&edst[r0], sd[t][0]); }
                    if (r1 < Nrows) { atomicAdd(&esrc[r1], ss[t][1]); atomicAdd(&edst[r1], sd[t][1]); }
                }
            }
        }
    }
}

// ---------------- pull aggregation: warp/node + softmax + bias + stats ------
__global__ void pull_stats(const int* __restrict__ off, const int* __restrict__ csr,
                           const float* __restrict__ h,
                           const float* __restrict__ esrc, const float* __restrict__ edst,
                           const float* __restrict__ bias, float* __restrict__ xout,
                           float* __restrict__ gsum, float* __restrict__ gsumsq)
{
    const int H = 4, D = 256, PER = 8;
    __shared__ float sm[PER * 256];

    int w = threadIdx.x >> 5;
    int lane = threadIdx.x & 31;
    int n = blockIdx.x * 8 + w;
    const int HH = lane >> 3;           // head owning my channels

    float v[PER];
#pragma unroll
    for (int i = 0; i < PER; i++) v[i] = 0.f;

    if (n < NNODES) {
        int c0 = lane * PER;
        float ed_w = edst[n * H + (lane & 3)];     // dst score for head (lane&3)
        float ed_l = (lane < H) ? ed_w : 0.f;

        // self loop
        float wl = 0.f;
        if (lane < H) wl = leaky_exp(esrc[n * H + lane] + ed_l);
        float myw = __shfl_sync(FULLMASK, wl, HH);
        float dn = myw;

        float acc[PER];
        {
            const float4* hp = reinterpret_cast<const float4*>(h + (size_t)n * D + c0);
            float4 p = hp[0], q = hp[1];
            acc[0] = myw * p.x; acc[1] = myw * p.y; acc[2] = myw * p.z; acc[3] = myw * p.w;
            acc[4] = myw * q.x; acc[5] = myw * q.y; acc[6] = myw * q.z; acc[7] = myw * q.w;
        }

        int jb = off[n], je = off[n + 1];
        int j = jb;
        for (; j + 3 < je; j += 4) {
            int s0 = csr[j], s1 = csr[j + 1], s2 = csr[j + 2], s3 = csr[j + 3];
            float wle = 0.f;
            if (lane < 16) {
                int e = lane >> 2;
                int se = (e == 0) ? s0 : (e == 1) ? s1 : (e == 2) ? s2 : s3;
                wle = leaky_exp(esrc[se * H + (lane & 3)] + ed_w);
            }
            float w0 = __shfl_sync(FULLMASK, wle, 0 + HH);
            float w1 = __shfl_sync(FULLMASK, wle, 4 + HH);
            float w2 = __shfl_sync(FULLMASK, wle, 8 + HH);
            float w3 = __shfl_sync(FULLMASK, wle, 12 + HH);
            dn += (w0 + w1) + (w2 + w3);

            const float4* hp0 = reinterpret_cast<const float4*>(h + (size_t)s0 * D + c0);
            const float4* hp1 = reinterpret_cast<const float4*>(h + (size_t)s1 * D + c0);
            const float4* hp2 = reinterpret_cast<const float4*>(h + (size_t)s2 * D + c0);
            const float4* hp3 = reinterpret_cast<const float4*>(h + (size_t)s3 * D + c0);
            float4 p0 = hp0[0], q0 = hp0[1];
            float4 p1 = hp1[0], q1 = hp1[1];
            float4 p2 = hp2[0], q2 = hp2[1];
            float4 p3 = hp3[0], q3 = hp3[1];
            acc[0] = fmaf(w0, p0.x, acc[0]); acc[1] = fmaf(w0, p0.y, acc[1]);
            acc[2] = fmaf(w0, p0.z, acc[2]); acc[3] = fmaf(w0, p0.w, acc[3]);
            acc[4] = fmaf(w0, q0.x, acc[4]); acc[5] = fmaf(w0, q0.y, acc[5]);
            acc[6] = fmaf(w0, q0.z, acc[6]); acc[7] = fmaf(w0, q0.w, acc[7]);
            acc[0] = fmaf(w1, p1.x, acc[0]); acc[1] = fmaf(w1, p1.y, acc[1]);
            acc[2] = fmaf(w1, p1.z, acc[2]); acc[3] = fmaf(w1, p1.w, acc[3]);
            acc[4] = fmaf(w1, q1.x, acc[4]); acc[5] = fmaf(w1, q1.y, acc[5]);
            acc[6] = fmaf(w1, q1.z, acc[6]); acc[7] = fmaf(w1, q1.w, acc[7]);
            acc[0] = fmaf(w2, p2.x, acc[0]); acc[1] = fmaf(w2, p2.y, acc[1]);
            acc[2] = fmaf(w2, p2.z, acc[2]); acc[3] = fmaf(w2, p2.w, acc[3]);
            acc[4] = fmaf(w2, q2.x, acc[4]); acc[5] = fmaf(w2, q2.y, acc[5]);
            acc[6] = fmaf(w2, q2.z, acc[6]); acc[7] = fmaf(w2, q2.w, acc[7]);
            acc[0] = fmaf(w3, p3.x, acc[0]); acc[1] = fmaf(w3, p3.y, acc[1]);
            acc[2] = fmaf(w3, p3.z, acc[2]); acc[3] = fmaf(w3, p3.w, acc[3]);
            acc[4] = fmaf(w3, q3.x, acc[4]); acc[5] = fmaf(w3, q3.y, acc[5]);
            acc[6] = fmaf(w3, q3.z, acc[6]); acc[7] = fmaf(w3, q3.w, acc[7]);
        }
        for (; j < je; j++) {
            int s = csr[j];
            float wl2 = 0.f;
            if (lane < H) wl2 = leaky_exp(esrc[s * H + lane] + ed_l);
            float we = __shfl_sync(FULLMASK, wl2, HH);
            dn += we;
            const float4* hp = reinterpret_cast<const float4*>(h + (size_t)s * D + c0);
            float4 p = hp[0], q = hp[1];
            acc[0] = fmaf(we, p.x, acc[0]); acc[1] = fmaf(we, p.y, acc[1]);
            acc[2] = fmaf(we, p.z, acc[2]); acc[3] = fmaf(we, p.w, acc[3]);
            acc[4] = fmaf(we, q.x, acc[4]); acc[5] = fmaf(we, q.y, acc[5]);
            acc[6] = fmaf(we, q.z, acc[6]); acc[7] = fmaf(we, q.w, acc[7]);
        }

        float inv = 1.f / (dn + 1e-16f);
#pragma unroll
        for (int i = 0; i < PER; i++) v[i] = fmaf(acc[i], inv, bias[c0 + i]);

        float4* xp = reinterpret_cast<float4*>(xout + (size_t)n * D + c0);
        xp[0] = make_float4(v[0], v[1], v[2], v[3]);
        xp[1] = make_float4(v[4], v[5], v[6], v[7]);
    }

    // fused per-block stats (conflict-free)
#pragma unroll
    for (int i = 0; i < PER; i++) sm[i * 256 + w * 32 + lane] = v[i];
    __syncthreads();

    int c = threadIdx.x;
    int li = c >> 3, ii = c & 7;
    float s = 0.f, s2 = 0.f;
#pragma unroll
    for (int ww = 0; ww < 8; ww++) {
        float x = sm[ii * 256 + ww * 32 + li];
        s += x;
        s2 += x * x;
    }
    atomicAdd(&gsum[c], s);
    atomicAdd(&gsumsq[c], s2);
}

// ---------------- layer-2 pull + output linear (unrolled x4) ----------------
__global__ void pull_out(const int* __restrict__ off, const int* __restrict__ csr,
                         const float* __restrict__ h,
                         const float* __restrict__ esrc, const float* __restrict__ edst,
                         const float* __restrict__ b2, const float* __restrict__ ow,
                         const float* __restrict__ ob, float* __restrict__ out)
{
    const int D = 128;
    int w = threadIdx.x >> 5;
    int lane = threadIdx.x & 31;
    int n = blockIdx.x * 8 + w;
    if (n >= NNODES) return;
    int c0 = lane * 4;

    float ed_l = edst[n];
    float wself = leaky_exp(esrc[n] + ed_l);
    float dn = wself;

    float acc0, acc1, acc2, acc3;
    {
        float4 p = *reinterpret_cast<const float4*>(h + (size_t)n * D + c0);
        acc0 = wself * p.x; acc1 = wself * p.y; acc2 = wself * p.z; acc3 = wself * p.w;
    }

    int jb = off[n], je = off[n + 1];
    int j = jb;
    for (; j + 3 < je; j += 4) {
        int s0 = csr[j], s1 = csr[j + 1], s2 = csr[j + 2], s3 = csr[j + 3];
        float wle = 0.f;
        if (lane < 4) {
            int se = (lane == 0) ? s0 : (lane == 1) ? s1 : (lane == 2) ? s2 : s3;
            wle = leaky_exp(esrc[se] + ed_l);
        }
        float w0 = __shfl_sync(FULLMASK, wle, 0);
        float w1 = __shfl_sync(FULLMASK, wle, 1);
        float w2 = __shfl_sync(FULLMASK, wle, 2);
        float w3 = __shfl_sync(FULLMASK, wle, 3);
        dn += (w0 + w1) + (w2 + w3);
        float4 p0 = *reinterpret_cast<const float4*>(h + (size_t)s0 * D + c0);
        float4 p1 = *reinterpret_cast<const float4*>(h + (size_t)s1 * D + c0);
        float4 p2 = *reinterpret_cast<const float4*>(h + (size_t)s2 * D + c0);
        float4 p3 = *reinterpret_cast<const float4*>(h + (size_t)s3 * D + c0);
        acc0 = fmaf(w0, p0.x, acc0); acc1 = fmaf(w0, p0.y, acc1);
        acc2 = fmaf(w0, p0.z, acc2); acc3 = fmaf(w0, p0.w, acc3);
        acc0 = fmaf(w1, p1.x, acc0); acc1 = fmaf(w1, p1.y, acc1);
        acc2 = fmaf(w1, p1.z, acc2); acc3 = fmaf(w1, p1.w, acc3);
        acc0 = fmaf(w2, p2.x, acc0); acc1 = fmaf(w2, p2.y, acc1);
        acc2 = fmaf(w2, p2.z, acc2); acc3 = fmaf(w2, p2.w, acc3);
        acc0 = fmaf(w3, p3.x, acc0); acc1 = fmaf(w3, p3.y, acc1);
        acc2 = fmaf(w3, p3.z, acc2); acc3 = fmaf(w3, p3.w, acc3);
    }
    for (; j < je; j++) {
        int s = csr[j];
        float wl2 = (lane == 0) ? leaky_exp(esrc[s] + ed_l) : 0.f;
        float we = __shfl_sync(FULLMASK, wl2, 0);
        dn += we;
        float4 p = *reinterpret_cast<const float4*>(h + (size_t)s * D + c0);
        acc0 = fmaf(we, p.x, acc0); acc1 = fmaf(we, p.y, acc1);
        acc2 = fmaf(we, p.z, acc2); acc3 = fmaf(we, p.w, acc3);
    }

    float inv = 1.f / (dn + 1e-16f);
    float4 bb = *reinterpret_cast<const float4*>(b2 + c0);
    float4 o0 = *reinterpret_cast<const float4*>(ow + c0);
    float4 o1 = *reinterpret_cast<const float4*>(ow + 128 + c0);
    float t0 = fmaf(acc0, inv, bb.x);
    float t1 = fmaf(acc1, inv, bb.y);
    float t2 = fmaf(acc2, inv, bb.z);
    float t3 = fmaf(acc3, inv, bb.w);
    float d0 = t0 * o0.x + t1 * o0.y + t2 * o0.z + t3 * o0.w;
    float d1 = t0 * o1.x + t1 * o1.y + t2 * o1.z + t3 * o1.w;
#pragma unroll
    for (int o = 16; o > 0; o >>= 1) {
        d0 += __shfl_xor_sync(FULLMASK, d0, o);
        d1 += __shfl_xor_sync(FULLMASK, d1, o);
    }
    if (lane == 0) {
        out[n * 2 + 0] = d0 + ob[0];
        out[n * 2 + 1] = d1 + ob[1];
    }
}

// ---------------- norm prep -------------------------------------------------
__global__ void norm_prep(float* __restrict__ gsum, float* __restrict__ gsumsq,
                          const float* __restrict__ gw, const float* __restrict__ gb,
                          const float* __restrict__ ms,
                          float* __restrict__ scale, float* __restrict__ shift)
{
    int c = threadIdx.x;
    const float invN = 1.f / (float)NNODES;
    float mean = gsum[c] * invN;
    float msq = gsumsq[c] * invN;
    float mm = mean * ms[c];
    float var = msq - 2.f * mm * mean + mm * mm;
    float sc = gw[c] * rsqrtf(var + EPS);
    scale[c] = sc;
    shift[c] = gb[c] - sc * mm;
    gsum[c] = 0.f;
    gsumsq[c] = 0.f;
}

// ---------------- launch ----------------------------------------------------
extern "C" void kernel_launch(void* const* d_in, const int* in_sizes, int n_in,
                              void* d_out, int out_size)
{
    const float* x      = (const float*)d_in[0];
    const int*   ei     = (const int*)d_in[1];
    const float* W0     = (const float*)d_in[2];
    const float* a_src0 = (const float*)d_in[3];
    const float* a_dst0 = (const float*)d_in[4];
    const float* b0     = (const float*)d_in[5];
    const float* gnw0   = (const float*)d_in[6];
    const float* gnb0   = (const float*)d_in[7];
    const float* gnms0  = (const float*)d_in[8];
    const float* W1     = (const float*)d_in[9];
    const float* a_src1 = (const float*)d_in[10];
    const float* a_dst1 = (const float*)d_in[11];
    const float* b1     = (const float*)d_in[12];
    const float* gnw1   = (const float*)d_in[13];
    const float* gnb1   = (const float*)d_in[14];
    const float* gnms1  = (const float*)d_in[15];
    const float* W2     = (const float*)d_in[16];
    const float* a_src2 = (const float*)d_in[17];
    const float* a_dst2 = (const float*)d_in[18];
    const float* b2     = (const float*)d_in[19];
    const float* ow     = (const float*)d_in[20];
    const float* ob     = (const float*)d_in[21];

    const int* srcp = ei;
    const int* dstp = ei + NEDGES;
    float* out = (float*)d_out;

    float *ph, *px, *pes, *ped, *pstats;
    int *pdeg, *poff, *ppos, *pcsr;
    cudaGetSymbolAddress((void**)&ph, g_h);
    cudaGetSymbolAddress((void**)&px, g_x);
    cudaGetSymbolAddress((void**)&pes, g_esrc);
    cudaGetSymbolAddress((void**)&ped, g_edst);
    cudaGetSymbolAddress((void**)&pstats, g_stats);
    cudaGetSymbolAddress((void**)&pdeg, g_deg);
    cudaGetSymbolAddress((void**)&poff, g_off);
    cudaGetSymbolAddress((void**)&ppos, g_pos);
    cudaGetSymbolAddress((void**)&pcsr, g_csr);
    float* gsum = pstats;
    float* gsumsq = pstats + 256;
    float* scale = pstats + 512;
    float* shift = pstats + 768;

    const int NODE_BLOCKS = (NNODES + 7) / 8;        // 6250
    const int EDGE_GRID = (NEDGES + 255) / 256;
    const int ROW_TILES = (NNODES + 127) / 128;      // 391
    dim3 gemm_grid0(2, ROW_TILES);                   // M=256
    dim3 gemm_grid2(1, ROW_TILES);                   // M=128

    // ---------- CSR build (once; reused by all 3 layers) ----------
    cudaMemsetAsync(pdeg, 0, NNODES * sizeof(int));
    cudaMemsetAsync(pstats, 0, 512 * sizeof(float));
    csr_count<<<EDGE_GRID, 256>>>(dstp, pdeg);
    csr_scan<<<1, 1024>>>(pdeg, poff, ppos);
    csr_fill<<<EDGE_GRID, 256>>>(srcp, dstp, ppos, pcsr);

    // ---------- layer 0 ----------
    gemm_tf32<0, 4><<<gemm_grid0, 256>>>(x, W0, ph, NNODES, 128, 256,
                                         nullptr, nullptr, a_src0, a_dst0, pes, ped);
    pull_stats<<<NODE_BLOCKS, 256>>>(poff, pcsr, ph, pes, ped, b0, px, gsum, gsumsq);
    norm_prep<<<1, 256>>>(gsum, gsumsq, gnw0, gnb0, gnms0, scale, shift);

    // ---------- layer 1 ----------
    gemm_tf32<1, 4><<<gemm_grid0, 256>>>(px, W1, ph, NNODES, 256, 256,
                                         scale, shift, a_src1, a_dst1, pes, ped);
    pull_stats<<<NODE_BLOCKS, 256>>>(poff, pcsr, ph, pes, ped, b1, px, gsum, gsumsq);
    norm_prep<<<1, 256>>>(gsum, gsumsq, gnw1, gnb1, gnms1, scale, shift);

    // ---------- layer 2 ----------
    cudaMemsetAsync(pes, 0, NNODES * sizeof(float));
    cudaMemsetAsync(ped, 0, NNODES * sizeof(float));
    gemm_tf32<1, 1><<<gemm_grid2, 256>>>(px, W2, ph, NNODES, 256, 128,
                                         scale, shift, a_src2, a_dst2, pes, ped);
    pull_out<<<NODE_BLOCKS, 256>>>(poff, pcsr, ph, pes, ped, b2, ow, ob, out);
}

// round 15
// speedup vs baseline: 1.1167x; 1.0425x over previous
#include <cuda_runtime.h>
#include <cstdint>

// ---------------- problem constants ----------------
#define NNODES 50000
#define NEDGES 400000
#define NEG_SLOPE 0.2f
#define EPS 1e-5f
#define FULLMASK 0xffffffffu

// ---------------- scratch (device globals; no allocs allowed) ----------------
__device__ float g_h  [NNODES * 256];
__device__ float g_x  [NNODES * 256];
__device__ float g_esrc[NNODES * 4];
__device__ float g_edst[NNODES * 4];
__device__ float g_stats[1024];         // [sum|sumsq|scale|shift] x 256
__device__ int   g_deg[NNODES];
__device__ int   g_off[NNODES + 1];
__device__ int   g_pos[NNODES];
__device__ int   g_csr[NEDGES];

// ---------------- helpers ----------------------------------------------------
__device__ __forceinline__ uint32_t f2tf32(float x) {
    uint32_t u;
    asm("cvt.rna.tf32.f32 %0, %1;" : "=r"(u) : "f"(x));
    return u;
}

__device__ __forceinline__ void mma_tf32(float& c0, float& c1, float& c2, float& c3,
                                         uint32_t a0, uint32_t a1, uint32_t a2, uint32_t a3,
                                         uint32_t b0, uint32_t b1) {
    asm volatile(
        "mma.sync.aligned.m16n8k8.row.col.f32.tf32.tf32.f32 "
        "{%0,%1,%2,%3}, {%4,%5,%6,%7}, {%8,%9}, {%0,%1,%2,%3};"
        : "+f"(c0), "+f"(c1), "+f"(c2), "+f"(c3)
        : "r"(a0), "r"(a1), "r"(a2), "r"(a3), "r"(b0), "r"(b1));
}

__device__ __forceinline__ void ldsm_x4(uint32_t& r0, uint32_t& r1,
                                        uint32_t& r2, uint32_t& r3, uint32_t addr) {
    asm volatile("ldmatrix.sync.aligned.m8n8.x4.shared.b16 {%0,%1,%2,%3}, [%4];"
                 : "=r"(r0), "=r"(r1), "=r"(r2), "=r"(r3) : "r"(addr));
}

__device__ __forceinline__ float leaky_exp(float e) {
    e = (e > 0.f) ? e : NEG_SLOPE * e;
    return __expf(e);
}

// ---------------- CSR build --------------------------------------------------
__global__ void csr_count(const int* __restrict__ dst, int* __restrict__ deg)
{
    int e = blockIdx.x * blockDim.x + threadIdx.x;
    if (e < NEDGES) atomicAdd(&deg[dst[e]], 1);
}

__global__ void csr_scan(const int* __restrict__ deg, int* __restrict__ off,
                         int* __restrict__ pos)
{
    const int CHUNK = (NNODES + 1023) / 1024;
    __shared__ int ss[1024];
    int t = threadIdx.x;
    int base = t * CHUNK;
    int s = 0;
    for (int k = 0; k < CHUNK; k++) {
        int i = base + k;
        if (i < NNODES) s += deg[i];
    }
    ss[t] = s;
    __syncthreads();
    for (int o = 1; o < 1024; o <<= 1) {
        int v = (t >= o) ? ss[t - o] : 0;
        __syncthreads();
        ss[t] += v;
        __syncthreads();
    }
    int run = (t > 0) ? ss[t - 1] : 0;
    for (int k = 0; k < CHUNK; k++) {
        int i = base + k;
        if (i < NNODES) {
            off[i] = run;
            pos[i] = run;
            run += deg[i];
        }
    }
    if (t == 1023) off[NNODES] = ss[1023];
}

__global__ void csr_fill(const int* __restrict__ src, const int* __restrict__ dst,
                         int* __restrict__ pos, int* __restrict__ csr)
{
    int e = blockIdx.x * blockDim.x + threadIdx.x;
    if (e < NEDGES) {
        int p = atomicAdd(&pos[dst[e]], 1);
        csr[p] = src[e];
    }
}

// ---------------- tf32 tensor-core GEMM + fused attn-score epilogue ----------
// R14 layout; fragment loads via ldmatrix.x4 (6 LDSM replace 24 LDS.32/kk-step).
template <int NORM, int HEADS>
__global__ void gemm_tf32(const float* __restrict__ X, const float* __restrict__ W,
                          float* __restrict__ C, int Nrows, int K, int M,
                          const float* __restrict__ scale, const float* __restrict__ shift,
                          const float* __restrict__ a_srcv, const float* __restrict__ a_dstv,
                          float* __restrict__ esrc, float* __restrict__ edst)
{
    __shared__ float As[128][36];
    __shared__ float Bs[128][36];

    const int tid = threadIdx.x;
    const int rowBase = blockIdx.y * 128;
    const int colBase = blockIdx.x * 128;
    const int warp = tid >> 5;
    const int lane = tid & 31;
    const int wr = (warp & 3) * 32;
    const int wc = (warp >> 2) * 64;
    const int grp = lane >> 2;
    const int tig = lane & 3;

    float c[2][8][4];
#pragma unroll
    for (int t = 0; t < 2; t++)
#pragma unroll
        for (int u = 0; u < 8; u++)
#pragma unroll
            for (int v = 0; v < 4; v++) c[t][u][v] = 0.f;

    // ldmatrix per-thread row addresses (bytes, shared space)
    const uint32_t asBase = (uint32_t)__cvta_generic_to_shared(&As[0][0]);
    const uint32_t bsBase = (uint32_t)__cvta_generic_to_shared(&Bs[0][0]);
    const int aRowL = ((lane >> 3) & 1) * 8 + (lane & 7);
    const int aCol  = (lane >> 4) * 4;
    const uint32_t aAddr0 = asBase + (uint32_t)(((wr + aRowL) * 36 + aCol) * 4);
    const uint32_t aAddr1 = asBase + (uint32_t)(((wr + 16 + aRowL) * 36 + aCol) * 4);
    const int bRowL = (lane >> 4) * 8 + (lane & 7);
    const int bCol  = ((lane >> 3) & 1) * 4;
    uint32_t bAddr[4];
#pragma unroll
    for (int g = 0; g < 4; g++)
        bAddr[g] = bsBase + (uint32_t)(((wc + g * 16 + bRowL) * 36 + bCol) * 4);

    for (int k0 = 0; k0 < K; k0 += 32) {
#pragma unroll
        for (int l = 0; l < 4; l++) {
            int idx = tid + l * 256;
            int r = idx >> 3;
            int kk = (idx & 7) * 4;
            int gr = rowBase + r;
            float4 v = make_float4(0.f, 0.f, 0.f, 0.f);
            if (gr < Nrows)
                v = *reinterpret_cast<const float4*>(X + (size_t)gr * K + k0 + kk);
            if (NORM) {
                float4 sc = *reinterpret_cast<const float4*>(scale + k0 + kk);
                float4 sh = *reinterpret_cast<const float4*>(shift + k0 + kk);
                v.x = fmaxf(fmaf(sc.x, v.x, sh.x), 0.f);
                v.y = fmaxf(fmaf(sc.y, v.y, sh.y), 0.f);
                v.z = fmaxf(fmaf(sc.z, v.z, sh.z), 0.f);
                v.w = fmaxf(fmaf(sc.w, v.w, sh.w), 0.f);
            }
            float4 sv;
            sv.x = __uint_as_float(f2tf32(v.x));
            sv.y = __uint_as_float(f2tf32(v.y));
            sv.z = __uint_as_float(f2tf32(v.z));
            sv.w = __uint_as_float(f2tf32(v.w));
            *reinterpret_cast<float4*>(&As[r][kk]) = sv;
        }
#pragma unroll
        for (int l = 0; l < 4; l++) {
            int idx = tid + l * 256;
            int r = idx >> 3;
            int kk = (idx & 7) * 4;
            float4 v = *reinterpret_cast<const float4*>(W + (size_t)(colBase + r) * K + k0 + kk);
            float4 sv;
            sv.x = __uint_as_float(f2tf32(v.x));
            sv.y = __uint_as_float(f2tf32(v.y));
            sv.z = __uint_as_float(f2tf32(v.z));
            sv.w = __uint_as_float(f2tf32(v.w));
            *reinterpret_cast<float4*>(&Bs[r][kk]) = sv;
        }
        __syncthreads();

#pragma unroll
        for (int kk = 0; kk < 32; kk += 8) {
            const uint32_t koff = (uint32_t)(kk * 4);
            uint32_t a[2][4];
            ldsm_x4(a[0][0], a[0][1], a[0][2], a[0][3], aAddr0 + koff);
            ldsm_x4(a[1][0], a[1][1], a[1][2], a[1][3], aAddr1 + koff);
            uint32_t b[8][2];
#pragma unroll
            for (int g = 0; g < 4; g++)
                ldsm_x4(b[2 * g][0], b[2 * g][1], b[2 * g + 1][0], b[2 * g + 1][1],
                        bAddr[g] + koff);
#pragma unroll
            for (int t = 0; t < 2; t++)
#pragma unroll
                for (int u = 0; u < 8; u++)
                    mma_tf32(c[t][u][0], c[t][u][1], c[t][u][2], c[t][u][3],
                             a[t][0], a[t][1], a[t][2], a[t][3], b[u][0], b[u][1]);
        }
        __syncthreads();
    }

    // store C
#pragma unroll
    for (int t = 0; t < 2; t++) {
        int gr0 = rowBase + wr + t * 16 + grp;
        int gr1 = gr0 + 8;
#pragma unroll
        for (int u = 0; u < 8; u++) {
            int gc = colBase + wc + u * 8 + tig * 2;
            if (gr0 < Nrows)
                *reinterpret_cast<float2*>(C + (size_t)gr0 * M + gc) =
                    make_float2(c[t][u][0], c[t][u][1]);
            if (gr1 < Nrows)
                *reinterpret_cast<float2*>(C + (size_t)gr1 * M + gc) =
                    make_float2(c[t][u][2], c[t][u][3]);
        }
    }

    // fused attention-score epilogue
    if (HEADS > 0) {
        float ss[2][2] = {{0.f, 0.f}, {0.f, 0.f}};
        float sd[2][2] = {{0.f, 0.f}, {0.f, 0.f}};
#pragma unroll
        for (int u = 0; u < 8; u++) {
            int gc = colBase + wc + u * 8 + tig * 2;
            float2 as = *reinterpret_cast<const float2*>(a_srcv + gc);
            float2 ad = *reinterpret_cast<const float2*>(a_dstv + gc);
#pragma unroll
            for (int t = 0; t < 2; t++) {
                ss[t][0] += c[t][u][0] * as.x + c[t][u][1] * as.y;
                ss[t][1] += c[t][u][2] * as.x + c[t][u][3] * as.y;
                sd[t][0] += c[t][u][0] * ad.x + c[t][u][1] * ad.y;
                sd[t][1] += c[t][u][2] * ad.x + c[t][u][3] * ad.y;
            }
        }
#pragma unroll
        for (int o = 1; o <= 2; o <<= 1) {
#pragma unroll
            for (int t = 0; t < 2; t++)
#pragma unroll
                for (int r = 0; r < 2; r++) {
                    ss[t][r] += __shfl_xor_sync(FULLMASK, ss[t][r], o);
                    sd[t][r] += __shfl_xor_sync(FULLMASK, sd[t][r], o);
                }
        }
        if (tig == 0) {
            int hw = (colBase + wc) >> ((HEADS == 4) ? 6 : 7);
#pragma unroll
            for (int t = 0; t < 2; t++) {
                int r0 = rowBase + wr + t * 16 + grp;
                int r1 = r0 + 8;
                if (HEADS == 4) {
                    if (r0 < Nrows) { esrc[r0 * 4 + hw] = ss[t][0]; edst[r0 * 4 + hw] = sd[t][0]; }
                    if (r1 < Nrows) { esrc[r1 * 4 + hw] = ss[t][1]; edst[r1 * 4 + hw] = sd[t][1]; }
                } else {
                    if (r0 < Nrows) { atomicAdd(&esrc[r0], ss[t][0]); atomicAdd(&edst[r0], sd[t][0]); }
                    if (r1 < Nrows) { atomicAdd(&esrc[r1], ss[t][1]); atomicAdd(&edst[r1], sd[t][1]); }
                }
            }
        }
    }
}

// ---------------- pull aggregation: warp/node + softmax + bias + stats ------
__global__ void pull_stats(const int* __restrict__ off, const int* __restrict__ csr,
                           const float* __restrict__ h,
                           const float* __restrict__ esrc, const float* __restrict__ edst,
                           const float* __restrict__ bias, float* __restrict__ xout,
                           float* __restrict__ gsum, float* __restrict__ gsumsq)
{
    const int H = 4, D = 256, PER = 8;
    __shared__ float sm[PER * 256];

    int w = threadIdx.x >> 5;
    int lane = threadIdx.x & 31;
    int n = blockIdx.x * 8 + w;
    const int HH = lane >> 3;           // head owning my channels

    float v[PER];
#pragma unroll
    for (int i = 0; i < PER; i++) v[i] = 0.f;

    if (n < NNODES) {
        int c0 = lane * PER;
        float ed_w = edst[n * H + (lane & 3)];     // dst score for head (lane&3)
        float ed_l = (lane < H) ? ed_w : 0.f;

        // self loop
        float wl = 0.f;
        if (lane < H) wl = leaky_exp(esrc[n * H + lane] + ed_l);
        float myw = __shfl_sync(FULLMASK, wl, HH);
        float dn = myw;

        float acc[PER];
        {
            const float4* hp = reinterpret_cast<const float4*>(h + (size_t)n * D + c0);
            float4 p = hp[0], q = hp[1];
            acc[0] = myw * p.x; acc[1] = myw * p.y; acc[2] = myw * p.z; acc[3] = myw * p.w;
            acc[4] = myw * q.x; acc[5] = myw * q.y; acc[6] = myw * q.z; acc[7] = myw * q.w;
        }

        int jb = off[n], je = off[n + 1];
        int j = jb;
        for (; j + 3 < je; j += 4) {
            int s0 = csr[j], s1 = csr[j + 1], s2 = csr[j + 2], s3 = csr[j + 3];
            float wle = 0.f;
            if (lane < 16) {
                int e = lane >> 2;
                int se = (e == 0) ? s0 : (e == 1) ? s1 : (e == 2) ? s2 : s3;
                wle = leaky_exp(esrc[se * H + (lane & 3)] + ed_w);
            }
            float w0 = __shfl_sync(FULLMASK, wle, 0 + HH);
            float w1 = __shfl_sync(FULLMASK, wle, 4 + HH);
            float w2 = __shfl_sync(FULLMASK, wle, 8 + HH);
            float w3 = __shfl_sync(FULLMASK, wle, 12 + HH);
            dn += (w0 + w1) + (w2 + w3);

            const float4* hp0 = reinterpret_cast<const float4*>(h + (size_t)s0 * D + c0);
            const float4* hp1 = reinterpret_cast<const float4*>(h + (size_t)s1 * D + c0);
            const float4* hp2 = reinterpret_cast<const float4*>(h + (size_t)s2 * D + c0);
            const float4* hp3 = reinterpret_cast<const float4*>(h + (size_t)s3 * D + c0);
            float4 p0 = hp0[0], q0 = hp0[1];
            float4 p1 = hp1[0], q1 = hp1[1];
            float4 p2 = hp2[0], q2 = hp2[1];
            float4 p3 = hp3[0], q3 = hp3[1];
            acc[0] = fmaf(w0, p0.x, acc[0]); acc[1] = fmaf(w0, p0.y, acc[1]);
            acc[2] = fmaf(w0, p0.z, acc[2]); acc[3] = fmaf(w0, p0.w, acc[3]);
            acc[4] = fmaf(w0, q0.x, acc[4]); acc[5] = fmaf(w0, q0.y, acc[5]);
            acc[6] = fmaf(w0, q0.z, acc[6]); acc[7] = fmaf(w0, q0.w, acc[7]);
            acc[0] = fmaf(w1, p1.x, acc[0]); acc[1] = fmaf(w1, p1.y, acc[1]);
            acc[2] = fmaf(w1, p1.z, acc[2]); acc[3] = fmaf(w1, p1.w, acc[3]);
            acc[4] = fmaf(w1, q1.x, acc[4]); acc[5] = fmaf(w1, q1.y, acc[5]);
            acc[6] = fmaf(w1, q1.z, acc[6]); acc[7] = fmaf(w1, q1.w, acc[7]);
            acc[0] = fmaf(w2, p2.x, acc[0]); acc[1] = fmaf(w2, p2.y, acc[1]);
            acc[2] = fmaf(w2, p2.z, acc[2]); acc[3] = fmaf(w2, p2.w, acc[3]);
            acc[4] = fmaf(w2, q2.x, acc[4]); acc[5] = fmaf(w2, q2.y, acc[5]);
            acc[6] = fmaf(w2, q2.z, acc[6]); acc[7] = fmaf(w2, q2.w, acc[7]);
            acc[0] = fmaf(w3, p3.x, acc[0]); acc[1] = fmaf(w3, p3.y, acc[1]);
            acc[2] = fmaf(w3, p3.z, acc[2]); acc[3] = fmaf(w3, p3.w, acc[3]);
            acc[4] = fmaf(w3, q3.x, acc[4]); acc[5] = fmaf(w3, q3.y, acc[5]);
            acc[6] = fmaf(w3, q3.z, acc[6]); acc[7] = fmaf(w3, q3.w, acc[7]);
        }
        for (; j < je; j++) {
            int s = csr[j];
            float wl2 = 0.f;
            if (lane < H) wl2 = leaky_exp(esrc[s * H + lane] + ed_l);
            float we = __shfl_sync(FULLMASK, wl2, HH);
            dn += we;
            const float4* hp = reinterpret_cast<const float4*>(h + (size_t)s * D + c0);
            float4 p = hp[0], q = hp[1];
            acc[0] = fmaf(we, p.x, acc[0]); acc[1] = fmaf(we, p.y, acc[1]);
            acc[2] = fmaf(we, p.z, acc[2]); acc[3] = fmaf(we, p.w, acc[3]);
            acc[4] = fmaf(we, q.x, acc[4]); acc[5] = fmaf(we, q.y, acc[5]);
            acc[6] = fmaf(we, q.z, acc[6]); acc[7] = fmaf(we, q.w, acc[7]);
        }

        float inv = 1.f / (dn + 1e-16f);
#pragma unroll
        for (int i = 0; i < PER; i++) v[i] = fmaf(acc[i], inv, bias[c0 + i]);

        float4* xp = reinterpret_cast<float4*>(xout + (size_t)n * D + c0);
        xp[0] = make_float4(v[0], v[1], v[2], v[3]);
        xp[1] = make_float4(v[4], v[5], v[6], v[7]);
    }

    // fused per-block stats (conflict-free)
#pragma unroll
    for (int i = 0; i < PER; i++) sm[i * 256 + w * 32 + lane] = v[i];
    __syncthreads();

    int c = threadIdx.x;
    int li = c >> 3, ii = c & 7;
    float s = 0.f, s2 = 0.f;
#pragma unroll
    for (int ww = 0; ww < 8; ww++) {
        float x = sm[ii * 256 + ww * 32 + li];
        s += x;
        s2 += x * x;
    }
    atomicAdd(&gsum[c], s);
    atomicAdd(&gsumsq[c], s2);
}

// ---------------- layer-2 pull + output linear (unrolled x4) ----------------
__global__ void pull_out(const int* __restrict__ off, const int* __restrict__ csr,
                         const float* __restrict__ h,
                         const float* __restrict__ esrc, const float* __restrict__ edst,
                         const float* __restrict__ b2, const float* __restrict__ ow,
                         const float* __restrict__ ob, float* __restrict__ out)
{
    const int D = 128;
    int w = threadIdx.x >> 5;
    int lane = threadIdx.x & 31;
    int n = blockIdx.x * 8 + w;
    if (n >= NNODES) return;
    int c0 = lane * 4;

    float ed_l = edst[n];
    float wself = leaky_exp(esrc[n] + ed_l);
    float dn = wself;

    float acc0, acc1, acc2, acc3;
    {
        float4 p = *reinterpret_cast<const float4*>(h + (size_t)n * D + c0);
        acc0 = wself * p.x; acc1 = wself * p.y; acc2 = wself * p.z; acc3 = wself * p.w;
    }

    int jb = off[n], je = off[n + 1];
    int j = jb;
    for (; j + 3 < je; j += 4) {
        int s0 = csr[j], s1 = csr[j + 1], s2 = csr[j + 2], s3 = csr[j + 3];
        float wle = 0.f;
        if (lane < 4) {
            int se = (lane == 0) ? s0 : (lane == 1) ? s1 : (lane == 2) ? s2 : s3;
            wle = leaky_exp(esrc[se] + ed_l);
        }
        float w0 = __shfl_sync(FULLMASK, wle, 0);
        float w1 = __shfl_sync(FULLMASK, wle, 1);
        float w2 = __shfl_sync(FULLMASK, wle, 2);
        float w3 = __shfl_sync(FULLMASK, wle, 3);
        dn += (w0 + w1) + (w2 + w3);
        float4 p0 = *reinterpret_cast<const float4*>(h + (size_t)s0 * D + c0);
        float4 p1 = *reinterpret_cast<const float4*>(h + (size_t)s1 * D + c0);
        float4 p2 = *reinterpret_cast<const float4*>(h + (size_t)s2 * D + c0);
        float4 p3 = *reinterpret_cast<const float4*>(h + (size_t)s3 * D + c0);
        acc0 = fmaf(w0, p0.x, acc0); acc1 = fmaf(w0, p0.y, acc1);
        acc2 = fmaf(w0, p0.z, acc2); acc3 = fmaf(w0, p0.w, acc3);
        acc0 = fmaf(w1, p1.x, acc0); acc1 = fmaf(w1, p1.y, acc1);
        acc2 = fmaf(w1, p1.z, acc2); acc3 = fmaf(w1, p1.w, acc3);
        acc0 = fmaf(w2, p2.x, acc0); acc1 = fmaf(w2, p2.y, acc1);
        acc2 = fmaf(w2, p2.z, acc2); acc3 = fmaf(w2, p2.w, acc3);
        acc0 = fmaf(w3, p3.x, acc0); acc1 = fmaf(w3, p3.y, acc1);
        acc2 = fmaf(w3, p3.z, acc2); acc3 = fmaf(w3, p3.w, acc3);
    }
    for (; j < je; j++) {
        int s = csr[j];
        float wl2 = (lane == 0) ? leaky_exp(esrc[s] + ed_l) : 0.f;
        float we = __shfl_sync(FULLMASK, wl2, 0);
        dn += we;
        float4 p = *reinterpret_cast<const float4*>(h + (size_t)s * D + c0);
        acc0 = fmaf(we, p.x, acc0); acc1 = fmaf(we, p.y, acc1);
        acc2 = fmaf(we, p.z, acc2); acc3 = fmaf(we, p.w, acc3);
    }

    float inv = 1.f / (dn + 1e-16f);
    float4 bb = *reinterpret_cast<const float4*>(b2 + c0);
    float4 o0 = *reinterpret_cast<const float4*>(ow + c0);
    float4 o1 = *reinterpret_cast<const float4*>(ow + 128 + c0);
    float t0 = fmaf(acc0, inv, bb.x);
    float t1 = fmaf(acc1, inv, bb.y);
    float t2 = fmaf(acc2, inv, bb.z);
    float t3 = fmaf(acc3, inv, bb.w);
    float d0 = t0 * o0.x + t1 * o0.y + t2 * o0.z + t3 * o0.w;
    float d1 = t0 * o1.x + t1 * o1.y + t2 * o1.z + t3 * o1.w;
#pragma unroll
    for (int o = 16; o > 0; o >>= 1) {
        d0 += __shfl_xor_sync(FULLMASK, d0, o);
        d1 += __shfl_xor_sync(FULLMASK, d1, o);
    }
    if (lane == 0) {
        out[n * 2 + 0] = d0 + ob[0];
        out[n * 2 + 1] = d1 + ob[1];
    }
}

// ---------------- norm prep -------------------------------------------------
__global__ void norm_prep(float* __restrict__ gsum, float* __restrict__ gsumsq,
                          const float* __restrict__ gw, const float* __restrict__ gb,
                          const float* __restrict__ ms,
                          float* __restrict__ scale, float* __restrict__ shift)
{
    int c = threadIdx.x;
    const float invN = 1.f / (float)NNODES;
    float mean = gsum[c] * invN;
    float msq = gsumsq[c] * invN;
    float mm = mean * ms[c];
    float var = msq - 2.f * mm * mean + mm * mm;
    float sc = gw[c] * rsqrtf(var + EPS);
    scale[c] = sc;
    shift[c] = gb[c] - sc * mm;
    gsum[c] = 0.f;
    gsumsq[c] = 0.f;
}

// ---------------- launch ----------------------------------------------------
extern "C" void kernel_launch(void* const* d_in, const int* in_sizes, int n_in,
                              void* d_out, int out_size)
{
    const float* x      = (const float*)d_in[0];
    const int*   ei     = (const int*)d_in[1];
    const float* W0     = (const float*)d_in[2];
    const float* a_src0 = (const float*)d_in[3];
    const float* a_dst0 = (const float*)d_in[4];
    const float* b0     = (const float*)d_in[5];
    const float* gnw0   = (const float*)d_in[6];
    const float* gnb0   = (const float*)d_in[7];
    const float* gnms0  = (const float*)d_in[8];
    const float* W1     = (const float*)d_in[9];
    const float* a_src1 = (const float*)d_in[10];
    const float* a_dst1 = (const float*)d_in[11];
    const float* b1     = (const float*)d_in[12];
    const float* gnw1   = (const float*)d_in[13];
    const float* gnb1   = (const float*)d_in[14];
    const float* gnms1  = (const float*)d_in[15];
    const float* W2     = (const float*)d_in[16];
    const float* a_src2 = (const float*)d_in[17];
    const float* a_dst2 = (const float*)d_in[18];
    const float* b2     = (const float*)d_in[19];
    const float* ow     = (const float*)d_in[20];
    const float* ob     = (const float*)d_in[21];

    const int* srcp = ei;
    const int* dstp = ei + NEDGES;
    float* out = (float*)d_out;

    float *ph, *px, *pes, *ped, *pstats;
    int *pdeg, *poff, *ppos, *pcsr;
    cudaGetSymbolAddress((void**)&ph, g_h);
    cudaGetSymbolAddress((void**)&px, g_x);
    cudaGetSymbolAddress((void**)&pes, g_esrc);
    cudaGetSymbolAddress((void**)&ped, g_edst);
    cudaGetSymbolAddress((void**)&pstats, g_stats);
    cudaGetSymbolAddress((void**)&pdeg, g_deg);
    cudaGetSymbolAddress((void**)&poff, g_off);
    cudaGetSymbolAddress((void**)&ppos, g_pos);
    cudaGetSymbolAddress((void**)&pcsr, g_csr);
    float* gsum = pstats;
    float* gsumsq = pstats + 256;
    float* scale = pstats + 512;
    float* shift = pstats + 768;

    const int NODE_BLOCKS = (NNODES + 7) / 8;        // 6250
    const int EDGE_GRID = (NEDGES + 255) / 256;
    const int ROW_TILES = (NNODES + 127) / 128;      // 391
    dim3 gemm_grid0(2, ROW_TILES);                   // M=256
    dim3 gemm_grid2(1, ROW_TILES);                   // M=128

    // ---------- CSR build (once; reused by all 3 layers) ----------
    cudaMemsetAsync(pdeg, 0, NNODES * sizeof(int));
    cudaMemsetAsync(pstats, 0, 512 * sizeof(float));
    csr_count<<<EDGE_GRID, 256>>>(dstp, pdeg);
    csr_scan<<<1, 1024>>>(pdeg, poff, ppos);
    csr_fill<<<EDGE_GRID, 256>>>(srcp, dstp, ppos, pcsr);

    // ---------- layer 0 ----------
    gemm_tf32<0, 4><<<gemm_grid0, 256>>>(x, W0, ph, NNODES, 128, 256,
                                         nullptr, nullptr, a_src0, a_dst0, pes, ped);
    pull_stats<<<NODE_BLOCKS, 256>>>(poff, pcsr, ph, pes, ped, b0, px, gsum, gsumsq);
    norm_prep<<<1, 256>>>(gsum, gsumsq, gnw0, gnb0, gnms0, scale, shift);

    // ---------- layer 1 ----------
    gemm_tf32<1, 4><<<gemm_grid0, 256>>>(px, W1, ph, NNODES, 256, 256,
                                         scale, shift, a_src1, a_dst1, pes, ped);
    pull_stats<<<NODE_BLOCKS, 256>>>(poff, pcsr, ph, pes, ped, b1, px, gsum, gsumsq);
    norm_prep<<<1, 256>>>(gsum, gsumsq, gnw1, gnb1, gnms1, scale, shift);

    // ---------- layer 2 ----------
    cudaMemsetAsync(pes, 0, NNODES * sizeof(float));
    cudaMemsetAsync(ped, 0, NNODES * sizeof(float));
    gemm_tf32<1, 1><<<gemm_grid2, 256>>>(px, W2, ph, NNODES, 256, 128,
                                         scale, shift, a_src2, a_dst2, pes, ped);
    pull_out<<<NODE_BLOCKS, 256>>>(poff, pcsr, ph, pes, ped, b2, ow, ob, out);
}